// round 2
// baseline (speedup 1.0000x reference)
#include <cuda_runtime.h>
#include <cstdint>
#include <cstdio>

// ---------------- constants ----------------
#define BB   32
#define DD   512
#define HH   8
#define DHH  64
#define ABB  8
#define KK   10          // NG+NW+NR = 2+5+3
#define SPD  1032        // padded seq (129*8); covers enc S=1025 and dec S=1024
#define FFD  2048
#define LATD 16
#define MSEQ 1024
#define MTOT (BB*SPD)    // 33024 rows, divisible by 64

// ---------------- scratch (device globals; no allocation) ----------------
__device__ float g_h  [(size_t)BB*SPD*DD];
__device__ float g_att[(size_t)BB*SPD*DD];
__device__ float g_qkv[(size_t)BB*SPD*3*DD];
__device__ float g_ff [(size_t)BB*SPD*FFD];
__device__ float g_z  [BB*LATD];
__device__ float g_seq[BB*2*MSEQ];
__device__ float g_elbo_b[BB];

// ---------------- encoder embedding ----------------
// h[b,0,:]   = emb_in[0]
// h[b,s,:]   = x[b,s-1,:16] @ W_data + b_data + emb_in[s]   (1<=s<1025)
// h[b,s,:]   = 0 for pad rows s in [1025,1032)
__global__ void embed_enc(const float* __restrict__ x, const float* __restrict__ Wd,
                          const float* __restrict__ bd, const float* __restrict__ emb)
{
    int idx = blockIdx.x * blockDim.x + threadIdx.x;
    if (idx >= BB*SPD*DD) return;
    int d = idx & 511;
    int s = (idx >> 9) % SPD;
    int b = idx / (SPD*DD);
    float v = 0.f;
    if (s < MSEQ + 1) {
        v = emb[s*DD + d];
        if (s > 0) {
            const float* xr = x + ((size_t)b*MSEQ + (s-1)) * 16;
            float acc = bd[d];
#pragma unroll
            for (int j = 0; j < 16; j++) acc += xr[j] * Wd[j*DD + d];
            v += acc;
        }
    }
    g_h[idx] = v;
}

// ---------------- generic SGEMM: C[M,N] = A[M,Kd] @ W[Kd,N] + bias, opt relu --------
// 64x64 tile, BK=16, 256 threads, 4x4 per thread. Requires M%64==0, N%64==0, Kd%16==0.
__global__ void gemm64(const float* __restrict__ A, const float* __restrict__ W,
                       const float* __restrict__ bias, float* __restrict__ C,
                       int N, int Kd, int relu)
{
    __shared__ float As[16][64];
    __shared__ float Ws[16][64];
    int tid  = threadIdx.x;
    int row0 = blockIdx.y * 64, col0 = blockIdx.x * 64;
    int ty = tid >> 4, tx = tid & 15;

    float acc[4][4] = {};

    int arow = tid >> 2;            // 0..63
    int ac4  = (tid & 3) * 4;       // 0,4,8,12
    int wrow = tid >> 4;            // 0..15
    int wc4  = (tid & 15) * 4;      // 0..60

    const float* Ag = A + (size_t)(row0 + arow) * Kd + ac4;
    const float* Wg = W + (size_t)wrow * N + col0 + wc4;

    for (int k0 = 0; k0 < Kd; k0 += 16) {
        float4 av = *(const float4*)(Ag + k0);
        float4 wv = *(const float4*)(Wg + (size_t)k0 * N);
        As[ac4+0][arow] = av.x; As[ac4+1][arow] = av.y;
        As[ac4+2][arow] = av.z; As[ac4+3][arow] = av.w;
        *(float4*)&Ws[wrow][wc4] = wv;
        __syncthreads();
#pragma unroll
        for (int kk = 0; kk < 16; kk++) {
            float4 a4 = *(const float4*)&As[kk][ty*4];
            float4 w4 = *(const float4*)&Ws[kk][tx*4];
            float a[4] = {a4.x, a4.y, a4.z, a4.w};
            float w[4] = {w4.x, w4.y, w4.z, w4.w};
#pragma unroll
            for (int i = 0; i < 4; i++)
#pragma unroll
                for (int j = 0; j < 4; j++) acc[i][j] += a[i] * w[j];
        }
        __syncthreads();
    }

#pragma unroll
    for (int i = 0; i < 4; i++) {
        int r = row0 + ty*4 + i;
        int c = col0 + tx*4;
        float4 v;
        v.x = acc[i][0] + bias[c+0];
        v.y = acc[i][1] + bias[c+1];
        v.z = acc[i][2] + bias[c+2];
        v.w = acc[i][3] + bias[c+3];
        if (relu) { v.x = fmaxf(v.x,0.f); v.y = fmaxf(v.y,0.f);
                    v.z = fmaxf(v.z,0.f); v.w = fmaxf(v.w,0.f); }
        *(float4*)&C[(size_t)r * N + c] = v;
    }
}

// ---------------- block-sparse attention ----------------
// one CTA per (block n, head h, batch b). 256 threads.
__global__ void attn_kernel(const float* __restrict__ qkv, float* __restrict__ out,
                            const int* __restrict__ rnd, int nb, int S)
{
    int n = blockIdx.x, h = blockIdx.y, b = blockIdx.z;
    int tid = threadIdx.x;

    __shared__ float qs[8][65];
    __shared__ float ks[80][65];
    __shared__ float vs[80][65];
    __shared__ float sc[8][80];
    __shared__ int   sbidx[KK];
    __shared__ int   svalid[KK];
    __shared__ float kmaskadd[80];

    if (tid < KK) {
        int j = tid, idx, valid = 1;
        if (j < 2)       { idx = j; }
        else if (j < 7)  { int w = n + j - 4; valid = (w >= 0 && w < nb);
                           idx = min(max(w, 0), nb - 1); }
        else             { idx = rnd[n*3 + (j - 7)]; }
        sbidx[j]  = idx;
        svalid[j] = valid;
    }
    __syncthreads();
    if (tid < 80) {
        int j = tid >> 3, p = tid & 7;
        int tok = sbidx[j]*ABB + p;
        kmaskadd[tid] = (svalid[j] && tok < S) ? 0.f : -1e9f;
    }

    const float* base = qkv + (size_t)b * SPD * (3*DD);
    for (int e = tid; e < 8*64; e += 256) {
        int p = e >> 6, d = e & 63;
        qs[p][d] = base[(size_t)(n*ABB + p)*(3*DD) + h*DHH + d];
    }
    for (int e = tid; e < 80*64; e += 256) {
        int kk = e >> 6, d = e & 63;
        int j = kk >> 3, p = kk & 7;
        int row = sbidx[j]*ABB + p;
        const float* rp = base + (size_t)row*(3*DD) + h*DHH + d;
        ks[kk][d] = rp[DD];
        vs[kk][d] = rp[2*DD];
    }
    __syncthreads();

    for (int e = tid; e < 640; e += 256) {
        int qi = e / 80, kk = e % 80;
        float s = 0.f;
#pragma unroll
        for (int d = 0; d < 64; d++) s += qs[qi][d] * ks[kk][d];
        sc[qi][kk] = s * 0.125f + kmaskadd[kk];
    }
    __syncthreads();

    int warp = tid >> 5, lane = tid & 31;
    if (warp < 8) {
        float v0 = sc[warp][lane];
        float v1 = sc[warp][lane + 32];
        float v2 = (lane < 16) ? sc[warp][lane + 64] : -1e30f;
        float m = fmaxf(fmaxf(v0, v1), v2);
        for (int o = 16; o; o >>= 1) m = fmaxf(m, __shfl_xor_sync(~0u, m, o));
        float e0 = __expf(v0 - m), e1 = __expf(v1 - m);
        float e2 = (lane < 16) ? __expf(v2 - m) : 0.f;
        float s = e0 + e1 + e2;
        for (int o = 16; o; o >>= 1) s += __shfl_xor_sync(~0u, s, o);
        float inv = 1.f / s;
        sc[warp][lane]      = e0 * inv;
        sc[warp][lane + 32] = e1 * inv;
        if (lane < 16) sc[warp][lane + 64] = e2 * inv;
    }
    __syncthreads();

    for (int e = tid; e < 8*64; e += 256) {
        int qi = e >> 6, d = e & 63;
        float acc = 0.f;
#pragma unroll
        for (int kk = 0; kk < 80; kk++) acc += sc[qi][kk] * vs[kk][d];
        out[((size_t)b*SPD + n*ABB + qi) * DD + h*DHH + d] = acc;
    }
}

// ---------------- fused residual add + LayerNorm (in place into h) ------------
__global__ void add_ln(float* __restrict__ h, const float* __restrict__ a,
                       const float* __restrict__ g, const float* __restrict__ be)
{
    int row = blockIdx.x;
    int tid = threadIdx.x;          // 256
    float* hr = h + (size_t)row * DD;
    const float* ar = a + (size_t)row * DD;
    float x0 = hr[tid]       + ar[tid];
    float x1 = hr[tid + 256] + ar[tid + 256];
    float s = x0 + x1, q = x0*x0 + x1*x1;
    for (int o = 16; o; o >>= 1) {
        s += __shfl_xor_sync(~0u, s, o);
        q += __shfl_xor_sync(~0u, q, o);
    }
    __shared__ float ss[8], sq[8];
    int w = tid >> 5, l = tid & 31;
    if (l == 0) { ss[w] = s; sq[w] = q; }
    __syncthreads();
    if (tid == 0) {
        float S = 0, Q = 0;
        for (int i = 0; i < 8; i++) { S += ss[i]; Q += sq[i]; }
        ss[0] = S * (1.f/512.f);
        sq[0] = Q * (1.f/512.f);
    }
    __syncthreads();
    float m = ss[0];
    float inv = rsqrtf(sq[0] - m*m + 1e-5f);
    hr[tid]       = (x0 - m) * inv * g[tid]       + be[tid];
    hr[tid + 256] = (x1 - m) * inv * g[tid + 256] + be[tid + 256];
}

// ---------------- latent head: mean/logvar/z + per-batch ELBO term ----------
__global__ void latent(const float* __restrict__ Wm, const float* __restrict__ bm,
                       const float* __restrict__ Wl, const float* __restrict__ bl,
                       const float* __restrict__ eps)
{
    int b = blockIdx.x, t = threadIdx.x;   // 16 threads
    const float* p = g_h + (size_t)b * SPD * DD;   // pooled = h[b,0,:]
    float m = bm[t], l = bl[t];
    for (int d = 0; d < DD; d++) {
        float pv = p[d];
        m += pv * Wm[d*LATD + t];
        l += pv * Wl[d*LATD + t];
    }
    g_z[b*LATD + t] = m + eps[b*LATD + t] * __expf(0.5f * l);
    float c = 1.f + l - m*m - __expf(l);
    for (int o = 8; o; o >>= 1) c += __shfl_xor_sync(0xffffu, c, o, 16);
    if (t == 0) g_elbo_b[b] = -0.5f * c;
}

// ---------------- seq = z @ W_exp + b_exp  (B x 2048) ----------------
__global__ void seq_expand(const float* __restrict__ We, const float* __restrict__ be)
{
    int idx = blockIdx.x * 256 + threadIdx.x;
    if (idx >= BB * 2 * MSEQ) return;
    int b = idx >> 11, o = idx & 2047;
    float s = be[o];
#pragma unroll
    for (int j = 0; j < 16; j++) s += g_z[b*16 + j] * We[j*2048 + o];
    g_seq[idx] = s;
}

// ---------------- decoder init: d = einsum(seq, W_conv) + b_conv + emb_out ----
__global__ void dec_init(const float* __restrict__ Wc, const float* __restrict__ bc,
                         const float* __restrict__ embo)
{
    int idx = blockIdx.x * 256 + threadIdx.x;
    if (idx >= BB * MSEQ * DD) return;
    int d = idx & 511;
    int s = (idx >> 9) & 1023;
    int b = idx >> 19;
    float v = g_seq[b*2048 + s]        * Wc[d]
            + g_seq[b*2048 + 1024 + s] * Wc[512 + d]
            + bc[d] + embo[s*DD + d];
    g_h[((size_t)b*SPD + s) * DD + d] = v;
}

// ---------------- output projection (B,1024,512) @ (512,16) -> d_out ---------
__global__ void out_proj(const float* __restrict__ Ws, const float* __restrict__ bs,
                         float* __restrict__ out)
{
    int idx = blockIdx.x * 256 + threadIdx.x;
    if (idx >= BB * MSEQ * 16) return;
    int j = idx & 15;
    int s = (idx >> 4) & 1023;
    int b = idx >> 14;
    const float* hr = g_h + ((size_t)b*SPD + s) * DD;
    float acc = bs[j];
    for (int d = 0; d < DD; d++) acc += hr[d] * Ws[d*16 + j];
    out[idx] = acc;
}

// ---------------- ELBO reduction ----------------
__global__ void elbo_fin(float* out, int out_size)
{
    if (threadIdx.x == 0 && out_size > BB*MSEQ*16) {
        float s = 0.f;
        for (int i = 0; i < BB; i++) s += g_elbo_b[i];
        out[BB*MSEQ*16] = s * (1.f / BB);
    }
}

// ---------------- launch ----------------
extern "C" void kernel_launch(void* const* d_in, const int* in_sizes, int n_in,
                              void* d_out, int out_size)
{
    const float* x       = (const float*)d_in[0];
    const float* eps     = (const float*)d_in[1];
    const float* emb_in  = (const float*)d_in[2];
    const float* emb_out = (const float*)d_in[3];
    const float* W_data  = (const float*)d_in[4];
    const float* b_data  = (const float*)d_in[5];
    const float* Wqkv    = (const float*)d_in[6];
    const float* bqkv    = (const float*)d_in[7];
    const float* Wo      = (const float*)d_in[8];
    const float* bo      = (const float*)d_in[9];
    const float* ln1_g   = (const float*)d_in[10];
    const float* ln1_b   = (const float*)d_in[11];
    const float* W1      = (const float*)d_in[12];
    const float* b1      = (const float*)d_in[13];
    const float* W2      = (const float*)d_in[14];
    const float* b2      = (const float*)d_in[15];
    const float* ln2_g   = (const float*)d_in[16];
    const float* ln2_b   = (const float*)d_in[17];
    const float* W_mean  = (const float*)d_in[18];
    const float* b_mean  = (const float*)d_in[19];
    const float* W_lv    = (const float*)d_in[20];
    const float* b_lv    = (const float*)d_in[21];
    const float* W_exp   = (const float*)d_in[22];
    const float* b_exp   = (const float*)d_in[23];
    const float* W_conv  = (const float*)d_in[24];
    const float* b_conv  = (const float*)d_in[25];
    const float* W_seq   = (const float*)d_in[26];
    const float* b_seq   = (const float*)d_in[27];
    const int*   rand_enc= (const int*)d_in[28];
    const int*   rand_dec= (const int*)d_in[29];

    float *h_, *att_, *qkv_, *ff_;
    cudaGetSymbolAddress((void**)&h_,   g_h);
    cudaGetSymbolAddress((void**)&att_, g_att);
    cudaGetSymbolAddress((void**)&qkv_, g_qkv);
    cudaGetSymbolAddress((void**)&ff_,  g_ff);

    const int M = MTOT;          // 33024

    embed_enc<<<(BB*SPD*DD + 255)/256, 256>>>(x, W_data, b_data, emb_in);

    for (int i = 0; i < 10; i++) {
        const int* rnd = (i < 5) ? rand_enc : rand_dec;
        int nb = (i < 5) ? 129 : 128;
        int S  = (i < 5) ? 1025 : 1024;

        // qkv = h @ Wqkv_i + bqkv_i
        gemm64<<<dim3((3*DD)/64, M/64), 256>>>(h_, Wqkv + (size_t)i*DD*3*DD,
                                               bqkv + (size_t)i*3*DD, qkv_, 3*DD, DD, 0);
        // sparse attention
        attn_kernel<<<dim3(nb, HH, BB), 256>>>(qkv_, att_, rnd, nb, S);
        // proj: tmp = att @ Wo + bo    (stored in g_ff scratch)
        gemm64<<<dim3(DD/64, M/64), 256>>>(att_, Wo + (size_t)i*DD*DD,
                                           bo + (size_t)i*DD, ff_, DD, DD, 0);
        // h = LN(h + tmp; ln1)
        add_ln<<<M, 256>>>(h_, ff_, ln1_g + (size_t)i*DD, ln1_b + (size_t)i*DD);
        // ff = relu(h @ W1 + b1)
        gemm64<<<dim3(FFD/64, M/64), 256>>>(h_, W1 + (size_t)i*DD*FFD,
                                            b1 + (size_t)i*FFD, ff_, FFD, DD, 1);
        // tmp2 = ff @ W2 + b2   (stored in g_att scratch)
        gemm64<<<dim3(DD/64, M/64), 256>>>(ff_, W2 + (size_t)i*FFD*DD,
                                           b2 + (size_t)i*DD, att_, DD, FFD, 0);
        // h = LN(h + tmp2; ln2)
        add_ln<<<M, 256>>>(h_, att_, ln2_g + (size_t)i*DD, ln2_b + (size_t)i*DD);

        if (i == 4) {
            latent<<<BB, 16>>>(W_mean, b_mean, W_lv, b_lv, eps);
            seq_expand<<<(BB*2*MSEQ + 255)/256, 256>>>(W_exp, b_exp);
            dec_init<<<(BB*MSEQ*DD + 255)/256, 256>>>(W_conv, b_conv, emb_out);
        }
    }

    out_proj<<<(BB*MSEQ*16 + 255)/256, 256>>>(W_seq, b_seq, (float*)d_out);
    elbo_fin<<<1, 32>>>((float*)d_out, out_size);
}

// round 3
// speedup vs baseline: 1.3172x; 1.3172x over previous
#include <cuda_runtime.h>
#include <cstdint>
#include <cstdio>

// ---------------- constants ----------------
#define BB   32
#define DD   512
#define HH   8
#define DHH  64
#define ABB  8
#define KK   10          // NG+NW+NR = 2+5+3
#define SPD  1032        // padded seq (129*8); covers enc S=1025 and dec S=1024
#define FFD  2048
#define LATD 16
#define MSEQ 1024
#define MTOT (BB*SPD)    // 33024 rows, divisible by 128

// ---------------- scratch (device globals; no allocation) ----------------
__device__ float g_h  [(size_t)BB*SPD*DD];
__device__ float g_att[(size_t)BB*SPD*DD];
__device__ float g_qkv[(size_t)BB*SPD*3*DD];
__device__ float g_ff [(size_t)BB*SPD*FFD];
__device__ float g_z  [BB*LATD];
__device__ float g_seq[BB*2*MSEQ];
__device__ float g_elbo_b[BB];

// ---------------- encoder embedding ----------------
__global__ void embed_enc(const float* __restrict__ x, const float* __restrict__ Wd,
                          const float* __restrict__ bd, const float* __restrict__ emb)
{
    int idx = blockIdx.x * blockDim.x + threadIdx.x;
    if (idx >= BB*SPD*DD) return;
    int d = idx & 511;
    int s = (idx >> 9) % SPD;
    int b = idx / (SPD*DD);
    float v = 0.f;
    if (s < MSEQ + 1) {
        v = emb[s*DD + d];
        if (s > 0) {
            const float* xr = x + ((size_t)b*MSEQ + (s-1)) * 16;
            float acc = bd[d];
#pragma unroll
            for (int j = 0; j < 16; j++) acc += xr[j] * Wd[j*DD + d];
            v += acc;
        }
    }
    g_h[idx] = v;
}

// ---------------- SGEMM: C[M,N] = A[M,Kd] @ W[Kd,N] + bias, opt relu ----------
// 128x128 tile, BK=8, 256 threads, 8x8 per thread, double-buffered smem.
// Requires M%128==0, N%128==0, Kd%8==0.
__global__ void __launch_bounds__(256)
gemm128(const float* __restrict__ A, const float* __restrict__ W,
        const float* __restrict__ bias, float* __restrict__ C,
        int N, int Kd, int relu)
{
    __shared__ float As[2][8][128];
    __shared__ float Ws[2][8][128];
    int tid  = threadIdx.x;
    int row0 = blockIdx.y * 128, col0 = blockIdx.x * 128;
    int tx = tid & 15, ty = tid >> 4;

    // global load assignment
    int arow = tid >> 1;           // 0..127
    int ac   = (tid & 1) * 4;      // 0 or 4
    int wrow = tid >> 5;           // 0..7
    int wc   = (tid & 31) * 4;     // 0..124

    const float* Ag = A + (size_t)(row0 + arow) * Kd + ac;
    const float* Wg = W + (size_t)wrow * N + col0 + wc;

    float acc[8][8] = {};

    // preload tile 0
    float4 av = *(const float4*)(Ag);
    float4 wv = *(const float4*)(Wg);
    As[0][ac+0][arow] = av.x; As[0][ac+1][arow] = av.y;
    As[0][ac+2][arow] = av.z; As[0][ac+3][arow] = av.w;
    *(float4*)&Ws[0][wrow][wc] = wv;
    __syncthreads();

    int KT = Kd >> 3;
    for (int kt = 0; kt < KT; kt++) {
        int cur = kt & 1, nxt = cur ^ 1;
        if (kt + 1 < KT) {
            av = *(const float4*)(Ag + (kt+1)*8);
            wv = *(const float4*)(Wg + (size_t)(kt+1)*8*N);
        }
#pragma unroll
        for (int k = 0; k < 8; k++) {
            float4 a0 = *(const float4*)&As[cur][k][ty*4];
            float4 a1 = *(const float4*)&As[cur][k][ty*4 + 64];
            float4 b0 = *(const float4*)&Ws[cur][k][tx*4];
            float4 b1 = *(const float4*)&Ws[cur][k][tx*4 + 64];
            float a[8] = {a0.x,a0.y,a0.z,a0.w,a1.x,a1.y,a1.z,a1.w};
            float b[8] = {b0.x,b0.y,b0.z,b0.w,b1.x,b1.y,b1.z,b1.w};
#pragma unroll
            for (int i = 0; i < 8; i++)
#pragma unroll
                for (int j = 0; j < 8; j++) acc[i][j] += a[i] * b[j];
        }
        if (kt + 1 < KT) {
            As[nxt][ac+0][arow] = av.x; As[nxt][ac+1][arow] = av.y;
            As[nxt][ac+2][arow] = av.z; As[nxt][ac+3][arow] = av.w;
            *(float4*)&Ws[nxt][wrow][wc] = wv;
            __syncthreads();
        }
    }

#pragma unroll
    for (int ih = 0; ih < 2; ih++)
#pragma unroll
    for (int i = 0; i < 4; i++) {
        int r = row0 + ty*4 + ih*64 + i;
#pragma unroll
        for (int jh = 0; jh < 2; jh++) {
            int c = col0 + tx*4 + jh*64;
            float4 v;
            v.x = acc[ih*4+i][jh*4+0] + bias[c+0];
            v.y = acc[ih*4+i][jh*4+1] + bias[c+1];
            v.z = acc[ih*4+i][jh*4+2] + bias[c+2];
            v.w = acc[ih*4+i][jh*4+3] + bias[c+3];
            if (relu) { v.x = fmaxf(v.x,0.f); v.y = fmaxf(v.y,0.f);
                        v.z = fmaxf(v.z,0.f); v.w = fmaxf(v.w,0.f); }
            *(float4*)&C[(size_t)r * N + c] = v;
        }
    }
}

// ---------------- block-sparse attention ----------------
__global__ void attn_kernel(const float* __restrict__ qkv, float* __restrict__ out,
                            const int* __restrict__ rnd, int nb, int S)
{
    int n = blockIdx.x, h = blockIdx.y, b = blockIdx.z;
    int tid = threadIdx.x;

    __shared__ float qs[8][65];
    __shared__ float ks[80][65];
    __shared__ float vs[80][65];
    __shared__ float sc[8][80];
    __shared__ int   sbidx[KK];
    __shared__ int   svalid[KK];
    __shared__ float kmaskadd[80];

    if (tid < KK) {
        int j = tid, idx, valid = 1;
        if (j < 2)       { idx = j; }
        else if (j < 7)  { int w = n + j - 4; valid = (w >= 0 && w < nb);
                           idx = min(max(w, 0), nb - 1); }
        else             { idx = rnd[n*3 + (j - 7)]; }
        sbidx[j]  = idx;
        svalid[j] = valid;
    }
    __syncthreads();
    if (tid < 80) {
        int j = tid >> 3, p = tid & 7;
        int tok = sbidx[j]*ABB + p;
        kmaskadd[tid] = (svalid[j] && tok < S) ? 0.f : -1e9f;
    }

    const float* base = qkv + (size_t)b * SPD * (3*DD);
    for (int e = tid; e < 8*64; e += 256) {
        int p = e >> 6, d = e & 63;
        qs[p][d] = base[(size_t)(n*ABB + p)*(3*DD) + h*DHH + d];
    }
    for (int e = tid; e < 80*64; e += 256) {
        int kk = e >> 6, d = e & 63;
        int j = kk >> 3, p = kk & 7;
        int row = sbidx[j]*ABB + p;
        const float* rp = base + (size_t)row*(3*DD) + h*DHH + d;
        ks[kk][d] = rp[DD];
        vs[kk][d] = rp[2*DD];
    }
    __syncthreads();

    for (int e = tid; e < 640; e += 256) {
        int qi = e / 80, kk = e % 80;
        float s = 0.f;
#pragma unroll
        for (int d = 0; d < 64; d++) s += qs[qi][d] * ks[kk][d];
        sc[qi][kk] = s * 0.125f + kmaskadd[kk];
    }
    __syncthreads();

    int warp = tid >> 5, lane = tid & 31;
    if (warp < 8) {
        float v0 = sc[warp][lane];
        float v1 = sc[warp][lane + 32];
        float v2 = (lane < 16) ? sc[warp][lane + 64] : -1e30f;
        float m = fmaxf(fmaxf(v0, v1), v2);
        for (int o = 16; o; o >>= 1) m = fmaxf(m, __shfl_xor_sync(~0u, m, o));
        float e0 = __expf(v0 - m), e1 = __expf(v1 - m);
        float e2 = (lane < 16) ? __expf(v2 - m) : 0.f;
        float s = e0 + e1 + e2;
        for (int o = 16; o; o >>= 1) s += __shfl_xor_sync(~0u, s, o);
        float inv = 1.f / s;
        sc[warp][lane]      = e0 * inv;
        sc[warp][lane + 32] = e1 * inv;
        if (lane < 16) sc[warp][lane + 64] = e2 * inv;
    }
    __syncthreads();

    for (int e = tid; e < 8*64; e += 256) {
        int qi = e >> 6, d = e & 63;
        float acc = 0.f;
#pragma unroll
        for (int kk = 0; kk < 80; kk++) acc += sc[qi][kk] * vs[kk][d];
        out[((size_t)b*SPD + n*ABB + qi) * DD + h*DHH + d] = acc;
    }
}

// ---------------- fused residual add + LayerNorm (in place into h) ------------
__global__ void add_ln(float* __restrict__ h, const float* __restrict__ a,
                       const float* __restrict__ g, const float* __restrict__ be)
{
    int row = blockIdx.x;
    int tid = threadIdx.x;          // 256
    float* hr = h + (size_t)row * DD;
    const float* ar = a + (size_t)row * DD;
    float x0 = hr[tid]       + ar[tid];
    float x1 = hr[tid + 256] + ar[tid + 256];
    float s = x0 + x1, q = x0*x0 + x1*x1;
    for (int o = 16; o; o >>= 1) {
        s += __shfl_xor_sync(~0u, s, o);
        q += __shfl_xor_sync(~0u, q, o);
    }
    __shared__ float ss[8], sq[8];
    int w = tid >> 5, l = tid & 31;
    if (l == 0) { ss[w] = s; sq[w] = q; }
    __syncthreads();
    if (tid == 0) {
        float S = 0, Q = 0;
        for (int i = 0; i < 8; i++) { S += ss[i]; Q += sq[i]; }
        ss[0] = S * (1.f/512.f);
        sq[0] = Q * (1.f/512.f);
    }
    __syncthreads();
    float m = ss[0];
    float inv = rsqrtf(sq[0] - m*m + 1e-5f);
    hr[tid]       = (x0 - m) * inv * g[tid]       + be[tid];
    hr[tid + 256] = (x1 - m) * inv * g[tid + 256] + be[tid + 256];
}

// ---------------- latent head ----------
__global__ void latent(const float* __restrict__ Wm, const float* __restrict__ bm,
                       const float* __restrict__ Wl, const float* __restrict__ bl,
                       const float* __restrict__ eps)
{
    int b = blockIdx.x, t = threadIdx.x;   // 16 threads
    const float* p = g_h + (size_t)b * SPD * DD;   // pooled = h[b,0,:]
    float m = bm[t], l = bl[t];
    for (int d = 0; d < DD; d++) {
        float pv = p[d];
        m += pv * Wm[d*LATD + t];
        l += pv * Wl[d*LATD + t];
    }
    g_z[b*LATD + t] = m + eps[b*LATD + t] * __expf(0.5f * l);
    float c = 1.f + l - m*m - __expf(l);
    for (int o = 8; o; o >>= 1) c += __shfl_xor_sync(0xffffu, c, o, 16);
    if (t == 0) g_elbo_b[b] = -0.5f * c;
}

// ---------------- seq = z @ W_exp + b_exp  (B x 2048) ----------------
__global__ void seq_expand(const float* __restrict__ We, const float* __restrict__ be)
{
    int idx = blockIdx.x * 256 + threadIdx.x;
    if (idx >= BB * 2 * MSEQ) return;
    int b = idx >> 11, o = idx & 2047;
    float s = be[o];
#pragma unroll
    for (int j = 0; j < 16; j++) s += g_z[b*16 + j] * We[j*2048 + o];
    g_seq[idx] = s;
}

// ---------------- decoder init ----
__global__ void dec_init(const float* __restrict__ Wc, const float* __restrict__ bc,
                         const float* __restrict__ embo)
{
    int idx = blockIdx.x * 256 + threadIdx.x;
    if (idx >= BB * MSEQ * DD) return;
    int d = idx & 511;
    int s = (idx >> 9) & 1023;
    int b = idx >> 19;
    float v = g_seq[b*2048 + s]        * Wc[d]
            + g_seq[b*2048 + 1024 + s] * Wc[512 + d]
            + bc[d] + embo[s*DD + d];
    g_h[((size_t)b*SPD + s) * DD + d] = v;
}

// ---------------- pad rows of decoder h must be zero for GEMM safety ----------
__global__ void zero_pad_rows()
{
    int idx = blockIdx.x * 256 + threadIdx.x;
    int nper = (SPD - MSEQ) * DD;      // 8*512 per batch
    if (idx >= BB * nper) return;
    int b = idx / nper;
    int r = idx % nper;
    g_h[((size_t)b*SPD + MSEQ) * DD + r] = 0.f;
}

// ---------------- output projection ---------
__global__ void out_proj(const float* __restrict__ Ws, const float* __restrict__ bs,
                         float* __restrict__ out)
{
    int idx = blockIdx.x * 256 + threadIdx.x;
    if (idx >= BB * MSEQ * 16) return;
    int j = idx & 15;
    int s = (idx >> 4) & 1023;
    int b = idx >> 14;
    const float* hr = g_h + ((size_t)b*SPD + s) * DD;
    float acc = bs[j];
    for (int d = 0; d < DD; d++) acc += hr[d] * Ws[d*16 + j];
    out[idx] = acc;
}

// ---------------- ELBO reduction ----------------
__global__ void elbo_fin(float* out, int out_size)
{
    if (threadIdx.x == 0 && out_size > BB*MSEQ*16) {
        float s = 0.f;
        for (int i = 0; i < BB; i++) s += g_elbo_b[i];
        out[BB*MSEQ*16] = s * (1.f / BB);
    }
}

// ---------------- launch ----------------
extern "C" void kernel_launch(void* const* d_in, const int* in_sizes, int n_in,
                              void* d_out, int out_size)
{
    const float* x       = (const float*)d_in[0];
    const float* eps     = (const float*)d_in[1];
    const float* emb_in  = (const float*)d_in[2];
    const float* emb_out = (const float*)d_in[3];
    const float* W_data  = (const float*)d_in[4];
    const float* b_data  = (const float*)d_in[5];
    const float* Wqkv    = (const float*)d_in[6];
    const float* bqkv    = (const float*)d_in[7];
    const float* Wo      = (const float*)d_in[8];
    const float* bo      = (const float*)d_in[9];
    const float* ln1_g   = (const float*)d_in[10];
    const float* ln1_b   = (const float*)d_in[11];
    const float* W1      = (const float*)d_in[12];
    const float* b1      = (const float*)d_in[13];
    const float* W2      = (const float*)d_in[14];
    const float* b2      = (const float*)d_in[15];
    const float* ln2_g   = (const float*)d_in[16];
    const float* ln2_b   = (const float*)d_in[17];
    const float* W_mean  = (const float*)d_in[18];
    const float* b_mean  = (const float*)d_in[19];
    const float* W_lv    = (const float*)d_in[20];
    const float* b_lv    = (const float*)d_in[21];
    const float* W_exp   = (const float*)d_in[22];
    const float* b_exp   = (const float*)d_in[23];
    const float* W_conv  = (const float*)d_in[24];
    const float* b_conv  = (const float*)d_in[25];
    const float* W_seq   = (const float*)d_in[26];
    const float* b_seq   = (const float*)d_in[27];
    const int*   rand_enc= (const int*)d_in[28];
    const int*   rand_dec= (const int*)d_in[29];

    float *h_, *att_, *qkv_, *ff_;
    cudaGetSymbolAddress((void**)&h_,   g_h);
    cudaGetSymbolAddress((void**)&att_, g_att);
    cudaGetSymbolAddress((void**)&qkv_, g_qkv);
    cudaGetSymbolAddress((void**)&ff_,  g_ff);

    const int M = MTOT;          // 33024 = 258*128

    embed_enc<<<(BB*SPD*DD + 255)/256, 256>>>(x, W_data, b_data, emb_in);

    for (int i = 0; i < 10; i++) {
        const int* rnd = (i < 5) ? rand_enc : rand_dec;
        int nb = (i < 5) ? 129 : 128;
        int S  = (i < 5) ? 1025 : 1024;

        gemm128<<<dim3((3*DD)/128, M/128), 256>>>(h_, Wqkv + (size_t)i*DD*3*DD,
                                                  bqkv + (size_t)i*3*DD, qkv_, 3*DD, DD, 0);
        attn_kernel<<<dim3(nb, HH, BB), 256>>>(qkv_, att_, rnd, nb, S);
        gemm128<<<dim3(DD/128, M/128), 256>>>(att_, Wo + (size_t)i*DD*DD,
                                              bo + (size_t)i*DD, ff_, DD, DD, 0);
        add_ln<<<M, 256>>>(h_, ff_, ln1_g + (size_t)i*DD, ln1_b + (size_t)i*DD);
        gemm128<<<dim3(FFD/128, M/128), 256>>>(h_, W1 + (size_t)i*DD*FFD,
                                               b1 + (size_t)i*FFD, ff_, FFD, DD, 1);
        gemm128<<<dim3(DD/128, M/128), 256>>>(ff_, W2 + (size_t)i*FFD*DD,
                                              b2 + (size_t)i*DD, att_, DD, FFD, 0);
        add_ln<<<M, 256>>>(h_, att_, ln2_g + (size_t)i*DD, ln2_b + (size_t)i*DD);

        if (i == 4) {
            latent<<<BB, 16>>>(W_mean, b_mean, W_lv, b_lv, eps);
            seq_expand<<<(BB*2*MSEQ + 255)/256, 256>>>(W_exp, b_exp);
            dec_init<<<(BB*MSEQ*DD + 255)/256, 256>>>(W_conv, b_conv, emb_out);
            zero_pad_rows<<<(BB*(SPD-MSEQ)*DD + 255)/256, 256>>>();
        }
    }

    out_proj<<<(BB*MSEQ*16 + 255)/256, 256>>>(W_seq, b_seq, (float*)d_out);
    elbo_fin<<<1, 32>>>((float*)d_out, out_size);
}

// round 5
// speedup vs baseline: 2.1114x; 1.6029x over previous
#include <cuda_runtime.h>
#include <cuda_bf16.h>
#include <cstdint>
#include <cstdio>

// ---------------- constants ----------------
#define BB   32
#define DD   512
#define HH   8
#define DHH  64
#define ABB  8
#define KK   10
#define SPD  1032
#define FFD  2048
#define LATD 16
#define MSEQ 1024
#define MTOT (BB*SPD)          // 33024 = 258*128

#define WB_PER_LAYER 3145728   // qkv 786432 + wo 262144 + w1 1048576 + w2 1048576

// ---------------- scratch (device globals; no allocation) ----------------
__device__ float g_h  [(size_t)BB*SPD*DD];
__device__ float g_att[(size_t)BB*SPD*DD];
__device__ float g_qkv[(size_t)BB*SPD*3*DD];
__device__ float g_ff [(size_t)BB*SPD*FFD];
__device__ float g_z  [BB*LATD];
__device__ float g_seq[BB*2*MSEQ];
__device__ float g_elbo_b[BB];
__device__ __align__(16) unsigned short g_wbh[(size_t)10*WB_PER_LAYER];
__device__ __align__(16) unsigned short g_wbl[(size_t)10*WB_PER_LAYER];
__device__ __align__(16) unsigned short g_abh[(size_t)MTOT*FFD];
__device__ __align__(16) unsigned short g_abl[(size_t)MTOT*FFD];

// ---------------- helpers ----------------
__device__ __forceinline__ void bsplit(float a, unsigned short& h, unsigned short& l)
{
    __nv_bfloat16 hb = __float2bfloat16_rn(a);
    h = __bfloat16_as_ushort(hb);
    float r = a - __bfloat162float(hb);
    l = __bfloat16_as_ushort(__float2bfloat16_rn(r));
}

#define CPA(smaddr, gptr) \
    asm volatile("cp.async.cg.shared.global [%0], [%1], 16;" :: "r"(smaddr), "l"(gptr))
#define CPC()  asm volatile("cp.async.commit_group;" ::: "memory")
#define CPW1() asm volatile("cp.async.wait_group 1;" ::: "memory")

__device__ __forceinline__ void ldsm4(uint32_t* r, uint32_t addr)
{
    asm volatile("ldmatrix.sync.aligned.m8n8.x4.shared.b16 {%0,%1,%2,%3}, [%4];"
        : "=r"(r[0]), "=r"(r[1]), "=r"(r[2]), "=r"(r[3]) : "r"(addr));
}
__device__ __forceinline__ void mma_bf16(float* d, const uint32_t* a, const uint32_t* b)
{
    asm volatile("mma.sync.aligned.m16n8k16.row.col.f32.bf16.bf16.f32 "
        "{%0,%1,%2,%3}, {%4,%5,%6,%7}, {%8,%9}, {%0,%1,%2,%3};"
        : "+f"(d[0]), "+f"(d[1]), "+f"(d[2]), "+f"(d[3])
        : "r"(a[0]), "r"(a[1]), "r"(a[2]), "r"(a[3]), "r"(b[0]), "r"(b[1]));
}

// smem geometry for gemm
#define STRB   144                 // bytes per tile row (72 halves)
#define TILEB  (128*STRB)          // 18432
#define BUFB   (4*TILEB)           // 73728: Ah, Al, Wh, Wl
#define SM_BUF 1024                // bias at 0..512
#define SMEM_GEMM (SM_BUF + 2*BUFB)   // 148480

// ---------------- weight transpose + bf16 split: W[K,N] -> Wb[N,K] hi/lo ------
__global__ void wconv(const float* __restrict__ W, unsigned short* __restrict__ hi,
                      unsigned short* __restrict__ lo, int K, int N)
{
    __shared__ float t[32][33];
    int k0 = blockIdx.y * 32, n0 = blockIdx.x * 32;
    int tx = threadIdx.x, ty = threadIdx.y;   // 32 x 8
#pragma unroll
    for (int i = 0; i < 32; i += 8)
        t[ty + i][tx] = W[(size_t)(k0 + ty + i) * N + n0 + tx];
    __syncthreads();
#pragma unroll
    for (int i = 0; i < 32; i += 8) {
        float v = t[tx][ty + i];
        unsigned short h, l;
        bsplit(v, h, l);
        size_t o = (size_t)(n0 + ty + i) * K + k0 + tx;
        hi[o] = h; lo[o] = l;
    }
}

// ---------------- activation bf16 split: A fp32 -> hi/lo bf16 (same layout) ----
__global__ void asplit(const float* __restrict__ A, unsigned short* __restrict__ hi,
                       unsigned short* __restrict__ lo, int n4)
{
    int i = blockIdx.x * 256 + threadIdx.x;
    if (i >= n4) return;
    float4 v = *(const float4*)(A + (size_t)i*4);
    unsigned short h0,h1,h2,h3,l0,l1,l2,l3;
    bsplit(v.x,h0,l0); bsplit(v.y,h1,l1); bsplit(v.z,h2,l2); bsplit(v.w,h3,l3);
    uint2 H = make_uint2((uint32_t)h0 | ((uint32_t)h1<<16), (uint32_t)h2 | ((uint32_t)h3<<16));
    uint2 L = make_uint2((uint32_t)l0 | ((uint32_t)l1<<16), (uint32_t)l2 | ((uint32_t)l3<<16));
    *(uint2*)(hi + (size_t)i*4) = H;
    *(uint2*)(lo + (size_t)i*4) = L;
}

// ---------------- tensor-core GEMM (mma.sync bf16, 3-pass split) --------------
// C[M,N] = A @ W^T + bias.  A hi/lo bf16 [M,Kd]; W hi/lo bf16 [N,Kd].
__global__ void __launch_bounds__(256) gemm_tc(
    const unsigned short* __restrict__ Ah, const unsigned short* __restrict__ Al,
    const unsigned short* __restrict__ Wh, const unsigned short* __restrict__ Wl,
    const float* __restrict__ bias, float* __restrict__ C, int N, int Kd, int relu)
{
    extern __shared__ char smem[];
    const int tid = threadIdx.x;
    const int lane = tid & 31, wid = tid >> 5;
    const int wr = wid >> 2, wc = wid & 3;          // 2 x 4 warp grid
    const int m0 = blockIdx.y * 128, n0 = blockIdx.x * 128;

    uint32_t sb;
    asm("{ .reg .u64 t; cvta.to.shared.u64 t, %1; cvt.u32.u64 %0, t; }"
        : "=r"(sb) : "l"(smem));

    float* biasS = (float*)smem;
    if (tid < 128) biasS[tid] = bias[n0 + tid];

    const int CHK = Kd >> 6;

    // per-chunk tile loader: 1024 16B segs / tile, 4 per thread
#define LOAD_TILE(dstoff, gbase)                                                 \
    {                                                                            \
        _Pragma("unroll")                                                        \
        for (int it = 0; it < 4; it++) {                                         \
            int s = it*256 + tid;                                                \
            int r = s >> 3, seg = s & 7;                                         \
            const unsigned short* gp = (gbase) + (size_t)r * Kd + seg*8;         \
            CPA(sb + (dstoff) + r*STRB + seg*16, gp);                            \
        }                                                                        \
    }

#define LOAD_CHUNK(buf, c)                                                       \
    {                                                                            \
        const unsigned short* aho = Ah + (size_t)m0*Kd + (c)*64;                 \
        const unsigned short* alo = Al + (size_t)m0*Kd + (c)*64;                 \
        const unsigned short* who = Wh + (size_t)n0*Kd + (c)*64;                 \
        const unsigned short* wlo = Wl + (size_t)n0*Kd + (c)*64;                 \
        LOAD_TILE(SM_BUF + (buf)*BUFB + 0*TILEB, aho);                           \
        LOAD_TILE(SM_BUF + (buf)*BUFB + 1*TILEB, alo);                           \
        LOAD_TILE(SM_BUF + (buf)*BUFB + 2*TILEB, who);                           \
        LOAD_TILE(SM_BUF + (buf)*BUFB + 3*TILEB, wlo);                           \
        CPC();                                                                   \
    }

    LOAD_CHUNK(0, 0);
    LOAD_CHUNK(1, 1);

    float acc[4][4][4] = {};

    const uint32_t aoff = (wr*64 + (lane & 15))*STRB + (lane >> 4)*16;
    const uint32_t boff = (wc*32 + (lane >> 4)*8 + (lane & 7))*STRB + ((lane >> 3) & 1)*16;

    for (int c = 0; c < CHK; c++) {
        CPW1();
        __syncthreads();
        uint32_t B = sb + SM_BUF + (c & 1)*BUFB;
#pragma unroll
        for (int ks = 0; ks < 4; ks++) {
            uint32_t ka = ks*32;
            uint32_t ah[4][4], al[4][4], bh[2][4], bl[2][4];
#pragma unroll
            for (int i = 0; i < 4; i++) {
                ldsm4(ah[i], B + 0*TILEB + aoff + i*16*STRB + ka);
                ldsm4(al[i], B + 1*TILEB + aoff + i*16*STRB + ka);
            }
#pragma unroll
            for (int g = 0; g < 2; g++) {
                ldsm4(bh[g], B + 2*TILEB + boff + g*16*STRB + ka);
                ldsm4(bl[g], B + 3*TILEB + boff + g*16*STRB + ka);
            }
#pragma unroll
            for (int i = 0; i < 4; i++)
#pragma unroll
            for (int j = 0; j < 4; j++) {
                const uint32_t* bhf = &bh[j >> 1][(j & 1)*2];
                const uint32_t* blf = &bl[j >> 1][(j & 1)*2];
                mma_bf16(acc[i][j], ah[i], bhf);
                mma_bf16(acc[i][j], al[i], bhf);
                mma_bf16(acc[i][j], ah[i], blf);
            }
        }
        __syncthreads();
        if (c + 2 < CHK) { LOAD_CHUNK(c & 1, c + 2); } else { CPC(); }
    }

    // epilogue
#pragma unroll
    for (int i = 0; i < 4; i++) {
        int row = m0 + wr*64 + i*16 + (lane >> 2);
#pragma unroll
        for (int j = 0; j < 4; j++) {
            int col = n0 + wc*32 + j*8 + (lane & 3)*2;
            float b0 = biasS[col - n0], b1 = biasS[col - n0 + 1];
            float2 v0, v1;
            v0.x = acc[i][j][0] + b0; v0.y = acc[i][j][1] + b1;
            v1.x = acc[i][j][2] + b0; v1.y = acc[i][j][3] + b1;
            if (relu) {
                v0.x = fmaxf(v0.x, 0.f); v0.y = fmaxf(v0.y, 0.f);
                v1.x = fmaxf(v1.x, 0.f); v1.y = fmaxf(v1.y, 0.f);
            }
            *(float2*)&C[(size_t)row * N + col] = v0;
            *(float2*)&C[(size_t)(row + 8) * N + col] = v1;
        }
    }
#undef LOAD_TILE
#undef LOAD_CHUNK
}

// ---------------- encoder embedding ----------------
__global__ void embed_enc(const float* __restrict__ x, const float* __restrict__ Wd,
                          const float* __restrict__ bd, const float* __restrict__ emb)
{
    int idx = blockIdx.x * blockDim.x + threadIdx.x;
    if (idx >= BB*SPD*DD) return;
    int d = idx & 511;
    int s = (idx >> 9) % SPD;
    int b = idx / (SPD*DD);
    float v = 0.f;
    if (s < MSEQ + 1) {
        v = emb[s*DD + d];
        if (s > 0) {
            const float* xr = x + ((size_t)b*MSEQ + (s-1)) * 16;
            float acc = bd[d];
#pragma unroll
            for (int j = 0; j < 16; j++) acc += xr[j] * Wd[j*DD + d];
            v += acc;
        }
    }
    g_h[idx] = v;
}

// ---------------- block-sparse attention ----------------
__global__ void attn_kernel(const float* __restrict__ qkv, float* __restrict__ out,
                            const int* __restrict__ rnd, int nb, int S)
{
    int n = blockIdx.x, h = blockIdx.y, b = blockIdx.z;
    int tid = threadIdx.x;

    __shared__ float qs[8][65];
    __shared__ float ks[80][65];
    __shared__ float vs[80][65];
    __shared__ float sc[8][80];
    __shared__ int   sbidx[KK];
    __shared__ int   svalid[KK];
    __shared__ float kmaskadd[80];

    if (tid < KK) {
        int j = tid, idx, valid = 1;
        if (j < 2)       { idx = j; }
        else if (j < 7)  { int w = n + j - 4; valid = (w >= 0 && w < nb);
                           idx = min(max(w, 0), nb - 1); }
        else             { idx = rnd[n*3 + (j - 7)]; }
        sbidx[j]  = idx;
        svalid[j] = valid;
    }
    __syncthreads();
    if (tid < 80) {
        int j = tid >> 3, p = tid & 7;
        int tok = sbidx[j]*ABB + p;
        kmaskadd[tid] = (svalid[j] && tok < S) ? 0.f : -1e9f;
    }

    const float* base = qkv + (size_t)b * SPD * (3*DD);
    for (int e = tid; e < 8*64; e += 256) {
        int p = e >> 6, d = e & 63;
        qs[p][d] = base[(size_t)(n*ABB + p)*(3*DD) + h*DHH + d];
    }
    for (int e = tid; e < 80*64; e += 256) {
        int kk = e >> 6, d = e & 63;
        int j = kk >> 3, p = kk & 7;
        int row = sbidx[j]*ABB + p;
        const float* rp = base + (size_t)row*(3*DD) + h*DHH + d;
        ks[kk][d] = rp[DD];
        vs[kk][d] = rp[2*DD];
    }
    __syncthreads();

    for (int e = tid; e < 640; e += 256) {
        int qi = e / 80, kk = e % 80;
        float s = 0.f;
#pragma unroll
        for (int d = 0; d < 64; d++) s += qs[qi][d] * ks[kk][d];
        sc[qi][kk] = s * 0.125f + kmaskadd[kk];
    }
    __syncthreads();

    int warp = tid >> 5, lane = tid & 31;
    if (warp < 8) {
        float v0 = sc[warp][lane];
        float v1 = sc[warp][lane + 32];
        float v2 = (lane < 16) ? sc[warp][lane + 64] : -1e30f;
        float m = fmaxf(fmaxf(v0, v1), v2);
        for (int o = 16; o; o >>= 1) m = fmaxf(m, __shfl_xor_sync(~0u, m, o));
        float e0 = __expf(v0 - m), e1 = __expf(v1 - m);
        float e2 = (lane < 16) ? __expf(v2 - m) : 0.f;
        float s = e0 + e1 + e2;
        for (int o = 16; o; o >>= 1) s += __shfl_xor_sync(~0u, s, o);
        float inv = 1.f / s;
        sc[warp][lane]      = e0 * inv;
        sc[warp][lane + 32] = e1 * inv;
        if (lane < 16) sc[warp][lane + 64] = e2 * inv;
    }
    __syncthreads();

    for (int e = tid; e < 8*64; e += 256) {
        int qi = e >> 6, d = e & 63;
        float acc = 0.f;
#pragma unroll
        for (int kk = 0; kk < 80; kk++) acc += sc[qi][kk] * vs[kk][d];
        out[((size_t)b*SPD + n*ABB + qi) * DD + h*DHH + d] = acc;
    }
}

// ---------------- fused residual add + LayerNorm ----------
__global__ void add_ln(float* __restrict__ h, const float* __restrict__ a,
                       const float* __restrict__ g, const float* __restrict__ be)
{
    int row = blockIdx.x;
    int tid = threadIdx.x;          // 256
    float* hr = h + (size_t)row * DD;
    const float* ar = a + (size_t)row * DD;
    float x0 = hr[tid]       + ar[tid];
    float x1 = hr[tid + 256] + ar[tid + 256];
    float s = x0 + x1, q = x0*x0 + x1*x1;
    for (int o = 16; o; o >>= 1) {
        s += __shfl_xor_sync(~0u, s, o);
        q += __shfl_xor_sync(~0u, q, o);
    }
    __shared__ float ss[8], sq[8];
    int w = tid >> 5, l = tid & 31;
    if (l == 0) { ss[w] = s; sq[w] = q; }
    __syncthreads();
    if (tid == 0) {
        float S = 0, Q = 0;
        for (int i = 0; i < 8; i++) { S += ss[i]; Q += sq[i]; }
        ss[0] = S * (1.f/512.f);
        sq[0] = Q * (1.f/512.f);
    }
    __syncthreads();
    float m = ss[0];
    float inv = rsqrtf(sq[0] - m*m + 1e-5f);
    hr[tid]       = (x0 - m) * inv * g[tid]       + be[tid];
    hr[tid + 256] = (x1 - m) * inv * g[tid + 256] + be[tid + 256];
}

// ---------------- latent head ----------
__global__ void latent(const float* __restrict__ Wm, const float* __restrict__ bm,
                       const float* __restrict__ Wl, const float* __restrict__ bl,
                       const float* __restrict__ eps)
{
    int b = blockIdx.x, t = threadIdx.x;   // 16 threads
    const float* p = g_h + (size_t)b * SPD * DD;
    float m = bm[t], l = bl[t];
    for (int d = 0; d < DD; d++) {
        float pv = p[d];
        m += pv * Wm[d*LATD + t];
        l += pv * Wl[d*LATD + t];
    }
    g_z[b*LATD + t] = m + eps[b*LATD + t] * __expf(0.5f * l);
    float c = 1.f + l - m*m - __expf(l);
    for (int o = 8; o; o >>= 1) c += __shfl_xor_sync(0xffffu, c, o, 16);
    if (t == 0) g_elbo_b[b] = -0.5f * c;
}

__global__ void seq_expand(const float* __restrict__ We, const float* __restrict__ be)
{
    int idx = blockIdx.x * 256 + threadIdx.x;
    if (idx >= BB * 2 * MSEQ) return;
    int b = idx >> 11, o = idx & 2047;
    float s = be[o];
#pragma unroll
    for (int j = 0; j < 16; j++) s += g_z[b*16 + j] * We[j*2048 + o];
    g_seq[idx] = s;
}

__global__ void dec_init(const float* __restrict__ Wc, const float* __restrict__ bc,
                         const float* __restrict__ embo)
{
    int idx = blockIdx.x * 256 + threadIdx.x;
    if (idx >= BB * MSEQ * DD) return;
    int d = idx & 511;
    int s = (idx >> 9) & 1023;
    int b = idx >> 19;
    float v = g_seq[b*2048 + s]        * Wc[d]
            + g_seq[b*2048 + 1024 + s] * Wc[512 + d]
            + bc[d] + embo[s*DD + d];
    g_h[((size_t)b*SPD + s) * DD + d] = v;
}

__global__ void zero_pad_rows()
{
    int idx = blockIdx.x * 256 + threadIdx.x;
    int nper = (SPD - MSEQ) * DD;
    if (idx >= BB * nper) return;
    int b = idx / nper;
    int r = idx % nper;
    g_h[((size_t)b*SPD + MSEQ) * DD + r] = 0.f;
}

__global__ void out_proj(const float* __restrict__ Ws, const float* __restrict__ bs,
                         float* __restrict__ out)
{
    int idx = blockIdx.x * 256 + threadIdx.x;
    if (idx >= BB * MSEQ * 16) return;
    int j = idx & 15;
    int s = (idx >> 4) & 1023;
    int b = idx >> 14;
    const float* hr = g_h + ((size_t)b*SPD + s) * DD;
    float acc = bs[j];
    for (int d = 0; d < DD; d++) acc += hr[d] * Ws[d*16 + j];
    out[idx] = acc;
}

__global__ void elbo_fin(float* out, int out_size)
{
    if (threadIdx.x == 0 && out_size > BB*MSEQ*16) {
        float s = 0.f;
        for (int i = 0; i < BB; i++) s += g_elbo_b[i];
        out[BB*MSEQ*16] = s * (1.f / BB);
    }
}

// ---------------- launch ----------------
extern "C" void kernel_launch(void* const* d_in, const int* in_sizes, int n_in,
                              void* d_out, int out_size)
{
    const float* x       = (const float*)d_in[0];
    const float* eps     = (const float*)d_in[1];
    const float* emb_in  = (const float*)d_in[2];
    const float* emb_out = (const float*)d_in[3];
    const float* W_data  = (const float*)d_in[4];
    const float* b_data  = (const float*)d_in[5];
    const float* Wqkv    = (const float*)d_in[6];
    const float* bqkv    = (const float*)d_in[7];
    const float* Wo      = (const float*)d_in[8];
    const float* bo      = (const float*)d_in[9];
    const float* ln1_g   = (const float*)d_in[10];
    const float* ln1_b   = (const float*)d_in[11];
    const float* W1      = (const float*)d_in[12];
    const float* b1      = (const float*)d_in[13];
    const float* W2      = (const float*)d_in[14];
    const float* b2      = (const float*)d_in[15];
    const float* ln2_g   = (const float*)d_in[16];
    const float* ln2_b   = (const float*)d_in[17];
    const float* W_mean  = (const float*)d_in[18];
    const float* b_mean  = (const float*)d_in[19];
    const float* W_lv    = (const float*)d_in[20];
    const float* b_lv    = (const float*)d_in[21];
    const float* W_exp   = (const float*)d_in[22];
    const float* b_exp   = (const float*)d_in[23];
    const float* W_conv  = (const float*)d_in[24];
    const float* b_conv  = (const float*)d_in[25];
    const float* W_seq   = (const float*)d_in[26];
    const float* b_seq   = (const float*)d_in[27];
    const int*   rand_enc= (const int*)d_in[28];
    const int*   rand_dec= (const int*)d_in[29];

    float *h_, *att_, *qkv_, *ff_;
    unsigned short *wbh_, *wbl_, *abh_, *abl_;
    cudaGetSymbolAddress((void**)&h_,   g_h);
    cudaGetSymbolAddress((void**)&att_, g_att);
    cudaGetSymbolAddress((void**)&qkv_, g_qkv);
    cudaGetSymbolAddress((void**)&ff_,  g_ff);
    cudaGetSymbolAddress((void**)&wbh_, g_wbh);
    cudaGetSymbolAddress((void**)&wbl_, g_wbl);
    cudaGetSymbolAddress((void**)&abh_, g_abh);
    cudaGetSymbolAddress((void**)&abl_, g_abl);

    cudaFuncSetAttribute(gemm_tc, cudaFuncAttributeMaxDynamicSharedMemorySize, SMEM_GEMM);

    const int M = MTOT;

    // convert all weights once per replay
    for (int i = 0; i < 10; i++) {
        size_t L = (size_t)i * WB_PER_LAYER;
        wconv<<<dim3(1536/32, 512/32), dim3(32,8)>>>(Wqkv + (size_t)i*512*1536,
                                                     wbh_ + L, wbl_ + L, 512, 1536);
        wconv<<<dim3(512/32, 512/32), dim3(32,8)>>>(Wo + (size_t)i*512*512,
                                                    wbh_ + L + 786432, wbl_ + L + 786432, 512, 512);
        wconv<<<dim3(2048/32, 512/32), dim3(32,8)>>>(W1 + (size_t)i*512*2048,
                                                     wbh_ + L + 1048576, wbl_ + L + 1048576, 512, 2048);
        wconv<<<dim3(512/32, 2048/32), dim3(32,8)>>>(W2 + (size_t)i*2048*512,
                                                     wbh_ + L + 2097152, wbl_ + L + 2097152, 2048, 512);
    }

    embed_enc<<<(BB*SPD*DD + 255)/256, 256>>>(x, W_data, b_data, emb_in);

    const int n4_512  = M*512/4;
    const int n4_2048 = M*2048/4;

    for (int i = 0; i < 10; i++) {
        const int* rnd = (i < 5) ? rand_enc : rand_dec;
        int nb = (i < 5) ? 129 : 128;
        int S  = (i < 5) ? 1025 : 1024;
        size_t L = (size_t)i * WB_PER_LAYER;

        // qkv = h @ Wqkv + b
        asplit<<<(n4_512 + 255)/256, 256>>>(h_, abh_, abl_, n4_512);
        gemm_tc<<<dim3(12, M/128), 256, SMEM_GEMM>>>(abh_, abl_, wbh_ + L, wbl_ + L,
            bqkv + (size_t)i*1536, qkv_, 1536, 512, 0);
        attn_kernel<<<dim3(nb, HH, BB), 256>>>(qkv_, att_, rnd, nb, S);
        // proj
        asplit<<<(n4_512 + 255)/256, 256>>>(att_, abh_, abl_, n4_512);
        gemm_tc<<<dim3(4, M/128), 256, SMEM_GEMM>>>(abh_, abl_, wbh_ + L + 786432, wbl_ + L + 786432,
            bo + (size_t)i*512, ff_, 512, 512, 0);
        add_ln<<<M, 256>>>(h_, ff_, ln1_g + (size_t)i*DD, ln1_b + (size_t)i*DD);
        // ffn
        asplit<<<(n4_512 + 255)/256, 256>>>(h_, abh_, abl_, n4_512);
        gemm_tc<<<dim3(16, M/128), 256, SMEM_GEMM>>>(abh_, abl_, wbh_ + L + 1048576, wbl_ + L + 1048576,
            b1 + (size_t)i*FFD, ff_, 2048, 512, 1);
        asplit<<<(n4_2048 + 255)/256, 256>>>(ff_, abh_, abl_, n4_2048);
        gemm_tc<<<dim3(4, M/128), 256, SMEM_GEMM>>>(abh_, abl_, wbh_ + L + 2097152, wbl_ + L + 2097152,
            b2 + (size_t)i*512, att_, 512, 2048, 0);
        add_ln<<<M, 256>>>(h_, att_, ln2_g + (size_t)i*DD, ln2_b + (size_t)i*DD);

        if (i == 4) {
            latent<<<BB, 16>>>(W_mean, b_mean, W_lv, b_lv, eps);
            seq_expand<<<(BB*2*MSEQ + 255)/256, 256>>>(W_exp, b_exp);
            dec_init<<<(BB*MSEQ*DD + 255)/256, 256>>>(W_conv, b_conv, emb_out);
            zero_pad_rows<<<(BB*(SPD-MSEQ)*DD + 255)/256, 256>>>();
        }
    }

    out_proj<<<(BB*MSEQ*16 + 255)/256, 256>>>(W_seq, b_seq, (float*)d_out);
    elbo_fin<<<1, 32>>>((float*)d_out, out_size);
}

// round 6
// speedup vs baseline: 3.4495x; 1.6337x over previous
#include <cuda_runtime.h>
#include <cuda_bf16.h>
#include <cuda_fp16.h>
#include <cstdint>
#include <cstdio>

// ---------------- constants ----------------
#define BB   32
#define DD   512
#define HH   8
#define DHH  64
#define ABB  8
#define KK   10
#define SPD  1032
#define FFD  2048
#define LATD 16
#define MSEQ 1024
#define MTOT (BB*SPD)          // 33024 = 258*128

#define WB_PER_LAYER 3145728   // qkv 786432 + wo 262144 + w1 1048576 + w2 1048576

// ---------------- scratch (device globals; no allocation) ----------------
__device__ float  g_h   [(size_t)BB*SPD*DD];
__device__ __align__(16) __half g_hh  [(size_t)BB*SPD*DD];
__device__ float  g_qkv [(size_t)BB*SPD*3*DD];
__device__ __align__(16) __half g_atth[(size_t)BB*SPD*DD];
__device__ float  g_tmp [(size_t)BB*SPD*DD];
__device__ __align__(16) __half g_ffh [(size_t)BB*SPD*FFD];
__device__ float  g_z   [BB*LATD];
__device__ float  g_seq [BB*2*MSEQ];
__device__ float  g_elbo_b[BB];
__device__ __align__(16) __half g_wb[(size_t)10*WB_PER_LAYER];

// ---------------- helpers ----------------
#define CPA(smaddr, gptr) \
    asm volatile("cp.async.cg.shared.global [%0], [%1], 16;" :: "r"(smaddr), "l"(gptr))
#define CPC()  asm volatile("cp.async.commit_group;" ::: "memory")
#define CPW1() asm volatile("cp.async.wait_group 1;" ::: "memory")

__device__ __forceinline__ void ldsm4(uint32_t* r, uint32_t addr)
{
    asm volatile("ldmatrix.sync.aligned.m8n8.x4.shared.b16 {%0,%1,%2,%3}, [%4];"
        : "=r"(r[0]), "=r"(r[1]), "=r"(r[2]), "=r"(r[3]) : "r"(addr));
}
__device__ __forceinline__ void mma_f16(float* d, const uint32_t* a, const uint32_t* b)
{
    asm volatile("mma.sync.aligned.m16n8k16.row.col.f32.f16.f16.f32 "
        "{%0,%1,%2,%3}, {%4,%5,%6,%7}, {%8,%9}, {%0,%1,%2,%3};"
        : "+f"(d[0]), "+f"(d[1]), "+f"(d[2]), "+f"(d[3])
        : "r"(a[0]), "r"(a[1]), "r"(a[2]), "r"(a[3]), "r"(b[0]), "r"(b[1]));
}

// smem geometry for gemm
#define STRB   144                 // bytes per tile row (72 halves)
#define TILEB  (128*STRB)          // 18432
#define BUFB   (2*TILEB)           // 36864: A, W
#define SM_BUF 1024
#define SMEM_GEMM (SM_BUF + 2*BUFB)   // 74752

// ---------------- weight transpose to fp16: W[K,N] -> Wh[N,K] ------
__global__ void wconv(const float* __restrict__ W, __half* __restrict__ hi, int K, int N)
{
    __shared__ float t[32][33];
    int k0 = blockIdx.y * 32, n0 = blockIdx.x * 32;
    int tx = threadIdx.x, ty = threadIdx.y;   // 32 x 8
#pragma unroll
    for (int i = 0; i < 32; i += 8)
        t[ty + i][tx] = W[(size_t)(k0 + ty + i) * N + n0 + tx];
    __syncthreads();
#pragma unroll
    for (int i = 0; i < 32; i += 8)
        hi[(size_t)(n0 + ty + i) * K + k0 + tx] = __float2half_rn(t[tx][ty + i]);
}

// ---------------- tensor-core GEMM (mma.sync fp16, single pass) --------------
// C[M,N] = A @ W^T + bias.  A fp16 [M,Kd]; W fp16 [N,Kd].
// mode 0: fp32 out.  mode 1: fp16 out with relu.
__global__ void __launch_bounds__(256) gemm_tc(
    const __half* __restrict__ A, const __half* __restrict__ W,
    const float* __restrict__ bias, void* __restrict__ Cv,
    int N, int Kd, int mode)
{
    extern __shared__ char smem[];
    const int tid = threadIdx.x;
    const int lane = tid & 31, wid = tid >> 5;
    const int wr = wid >> 2, wc = wid & 3;          // 2 x 4 warp grid
    const int m0 = blockIdx.y * 128, n0 = blockIdx.x * 128;

    uint32_t sb;
    asm("{ .reg .u64 t; cvta.to.shared.u64 t, %1; cvt.u32.u64 %0, t; }"
        : "=r"(sb) : "l"(smem));

    float* biasS = (float*)smem;
    if (tid < 128) biasS[tid] = bias[n0 + tid];

    const int CHK = Kd >> 6;

#define LOAD_TILE(dstoff, gbase)                                                 \
    {                                                                            \
        _Pragma("unroll")                                                        \
        for (int it = 0; it < 4; it++) {                                         \
            int s = it*256 + tid;                                                \
            int r = s >> 3, seg = s & 7;                                         \
            const __half* gp = (gbase) + (size_t)r * Kd + seg*8;                 \
            CPA(sb + (dstoff) + r*STRB + seg*16, gp);                            \
        }                                                                        \
    }

#define LOAD_CHUNK(buf, c)                                                       \
    {                                                                            \
        const __half* ao = A + (size_t)m0*Kd + (c)*64;                           \
        const __half* wo = W + (size_t)n0*Kd + (c)*64;                           \
        LOAD_TILE(SM_BUF + (buf)*BUFB + 0*TILEB, ao);                            \
        LOAD_TILE(SM_BUF + (buf)*BUFB + 1*TILEB, wo);                            \
        CPC();                                                                   \
    }

    LOAD_CHUNK(0, 0);
    LOAD_CHUNK(1, 1);

    float acc[4][4][4] = {};

    const uint32_t aoff = (wr*64 + (lane & 15))*STRB + (lane >> 4)*16;
    const uint32_t boff = (wc*32 + (lane >> 4)*8 + (lane & 7))*STRB + ((lane >> 3) & 1)*16;

    for (int c = 0; c < CHK; c++) {
        CPW1();
        __syncthreads();
        uint32_t B = sb + SM_BUF + (c & 1)*BUFB;
#pragma unroll
        for (int ks = 0; ks < 4; ks++) {
            uint32_t ka = ks*32;
            uint32_t ar[4][4], br[2][4];
#pragma unroll
            for (int i = 0; i < 4; i++)
                ldsm4(ar[i], B + 0*TILEB + aoff + i*16*STRB + ka);
#pragma unroll
            for (int g = 0; g < 2; g++)
                ldsm4(br[g], B + 1*TILEB + boff + g*16*STRB + ka);
#pragma unroll
            for (int i = 0; i < 4; i++)
#pragma unroll
            for (int j = 0; j < 4; j++)
                mma_f16(acc[i][j], ar[i], &br[j >> 1][(j & 1)*2]);
        }
        __syncthreads();
        if (c + 2 < CHK) { LOAD_CHUNK(c & 1, c + 2); } else { CPC(); }
    }

    // epilogue
#pragma unroll
    for (int i = 0; i < 4; i++) {
        int row = m0 + wr*64 + i*16 + (lane >> 2);
#pragma unroll
        for (int j = 0; j < 4; j++) {
            int col = n0 + wc*32 + j*8 + (lane & 3)*2;
            float b0 = biasS[col - n0], b1 = biasS[col - n0 + 1];
            float v00 = acc[i][j][0] + b0, v01 = acc[i][j][1] + b1;
            float v10 = acc[i][j][2] + b0, v11 = acc[i][j][3] + b1;
            if (mode == 1) {
                v00 = fmaxf(v00, 0.f); v01 = fmaxf(v01, 0.f);
                v10 = fmaxf(v10, 0.f); v11 = fmaxf(v11, 0.f);
                __half* Ch = (__half*)Cv;
                *(__half2*)&Ch[(size_t)row * N + col]       = __floats2half2_rn(v00, v01);
                *(__half2*)&Ch[(size_t)(row + 8) * N + col] = __floats2half2_rn(v10, v11);
            } else {
                float* C = (float*)Cv;
                *(float2*)&C[(size_t)row * N + col]       = make_float2(v00, v01);
                *(float2*)&C[(size_t)(row + 8) * N + col] = make_float2(v10, v11);
            }
        }
    }
#undef LOAD_TILE
#undef LOAD_CHUNK
}

// ---------------- encoder embedding (writes h fp32 + fp16) ----------------
__global__ void embed_enc(const float* __restrict__ x, const float* __restrict__ Wd,
                          const float* __restrict__ bd, const float* __restrict__ emb)
{
    int idx = blockIdx.x * blockDim.x + threadIdx.x;
    if (idx >= BB*SPD*DD) return;
    int d = idx & 511;
    int s = (idx >> 9) % SPD;
    int b = idx / (SPD*DD);
    float v = 0.f;
    if (s < MSEQ + 1) {
        v = emb[s*DD + d];
        if (s > 0) {
            const float* xr = x + ((size_t)b*MSEQ + (s-1)) * 16;
            float acc = bd[d];
#pragma unroll
            for (int j = 0; j < 16; j++) acc += xr[j] * Wd[j*DD + d];
            v += acc;
        }
    }
    g_h[idx] = v;
    g_hh[idx] = __float2half_rn(v);
}

// ---------------- block-sparse attention (fp16 output) ----------------
__global__ void attn_kernel(const float* __restrict__ qkv, __half* __restrict__ out,
                            const int* __restrict__ rnd, int nb, int S)
{
    int n = blockIdx.x, h = blockIdx.y, b = blockIdx.z;
    int tid = threadIdx.x;

    __shared__ float qs[8][65];
    __shared__ float ks[80][65];
    __shared__ float vs[80][65];
    __shared__ float sc[8][80];
    __shared__ int   sbidx[KK];
    __shared__ int   svalid[KK];
    __shared__ float kmaskadd[80];

    if (tid < KK) {
        int j = tid, idx, valid = 1;
        if (j < 2)       { idx = j; }
        else if (j < 7)  { int w = n + j - 4; valid = (w >= 0 && w < nb);
                           idx = min(max(w, 0), nb - 1); }
        else             { idx = rnd[n*3 + (j - 7)]; }
        sbidx[j]  = idx;
        svalid[j] = valid;
    }
    __syncthreads();
    if (tid < 80) {
        int j = tid >> 3, p = tid & 7;
        int tok = sbidx[j]*ABB + p;
        kmaskadd[tid] = (svalid[j] && tok < S) ? 0.f : -1e9f;
    }

    const float* base = qkv + (size_t)b * SPD * (3*DD);
    for (int e = tid; e < 8*64; e += 256) {
        int p = e >> 6, d = e & 63;
        qs[p][d] = base[(size_t)(n*ABB + p)*(3*DD) + h*DHH + d];
    }
    for (int e = tid; e < 80*64; e += 256) {
        int kk = e >> 6, d = e & 63;
        int j = kk >> 3, p = kk & 7;
        int row = sbidx[j]*ABB + p;
        const float* rp = base + (size_t)row*(3*DD) + h*DHH + d;
        ks[kk][d] = rp[DD];
        vs[kk][d] = rp[2*DD];
    }
    __syncthreads();

    for (int e = tid; e < 640; e += 256) {
        int qi = e / 80, kk = e % 80;
        float s = 0.f;
#pragma unroll
        for (int d = 0; d < 64; d++) s += qs[qi][d] * ks[kk][d];
        sc[qi][kk] = s * 0.125f + kmaskadd[kk];
    }
    __syncthreads();

    int warp = tid >> 5, lane = tid & 31;
    if (warp < 8) {
        float v0 = sc[warp][lane];
        float v1 = sc[warp][lane + 32];
        float v2 = (lane < 16) ? sc[warp][lane + 64] : -1e30f;
        float m = fmaxf(fmaxf(v0, v1), v2);
        for (int o = 16; o; o >>= 1) m = fmaxf(m, __shfl_xor_sync(~0u, m, o));
        float e0 = __expf(v0 - m), e1 = __expf(v1 - m);
        float e2 = (lane < 16) ? __expf(v2 - m) : 0.f;
        float s = e0 + e1 + e2;
        for (int o = 16; o; o >>= 1) s += __shfl_xor_sync(~0u, s, o);
        float inv = 1.f / s;
        sc[warp][lane]      = e0 * inv;
        sc[warp][lane + 32] = e1 * inv;
        if (lane < 16) sc[warp][lane + 64] = e2 * inv;
    }
    __syncthreads();

    for (int e = tid; e < 8*64; e += 256) {
        int qi = e >> 6, d = e & 63;
        float acc = 0.f;
#pragma unroll
        for (int kk = 0; kk < 80; kk++) acc += sc[qi][kk] * vs[kk][d];
        out[((size_t)b*SPD + n*ABB + qi) * DD + h*DHH + d] = __float2half_rn(acc);
    }
}

// ---------------- fused residual add + LayerNorm (writes fp32 + fp16) --------
__global__ void add_ln(float* __restrict__ h, __half* __restrict__ hh,
                       const float* __restrict__ a,
                       const float* __restrict__ g, const float* __restrict__ be)
{
    int row = blockIdx.x;
    int tid = threadIdx.x;          // 256
    float* hr = h + (size_t)row * DD;
    __half* hhr = hh + (size_t)row * DD;
    const float* ar = a + (size_t)row * DD;
    float x0 = hr[tid]       + ar[tid];
    float x1 = hr[tid + 256] + ar[tid + 256];
    float s = x0 + x1, q = x0*x0 + x1*x1;
    for (int o = 16; o; o >>= 1) {
        s += __shfl_xor_sync(~0u, s, o);
        q += __shfl_xor_sync(~0u, q, o);
    }
    __shared__ float ss[8], sq[8];
    int w = tid >> 5, l = tid & 31;
    if (l == 0) { ss[w] = s; sq[w] = q; }
    __syncthreads();
    if (tid == 0) {
        float S = 0, Q = 0;
        for (int i = 0; i < 8; i++) { S += ss[i]; Q += sq[i]; }
        ss[0] = S * (1.f/512.f);
        sq[0] = Q * (1.f/512.f);
    }
    __syncthreads();
    float m = ss[0];
    float inv = rsqrtf(sq[0] - m*m + 1e-5f);
    float y0 = (x0 - m) * inv * g[tid]       + be[tid];
    float y1 = (x1 - m) * inv * g[tid + 256] + be[tid + 256];
    hr[tid]        = y0;
    hr[tid + 256]  = y1;
    hhr[tid]       = __float2half_rn(y0);
    hhr[tid + 256] = __float2half_rn(y1);
}

// ---------------- latent head ----------
__global__ void latent(const float* __restrict__ Wm, const float* __restrict__ bm,
                       const float* __restrict__ Wl, const float* __restrict__ bl,
                       const float* __restrict__ eps)
{
    int b = blockIdx.x, t = threadIdx.x;   // 16 threads
    const float* p = g_h + (size_t)b * SPD * DD;
    float m = bm[t], l = bl[t];
    for (int d = 0; d < DD; d++) {
        float pv = p[d];
        m += pv * Wm[d*LATD + t];
        l += pv * Wl[d*LATD + t];
    }
    g_z[b*LATD + t] = m + eps[b*LATD + t] * __expf(0.5f * l);
    float c = 1.f + l - m*m - __expf(l);
    for (int o = 8; o; o >>= 1) c += __shfl_xor_sync(0xffffu, c, o, 16);
    if (t == 0) g_elbo_b[b] = -0.5f * c;
}

__global__ void seq_expand(const float* __restrict__ We, const float* __restrict__ be)
{
    int idx = blockIdx.x * 256 + threadIdx.x;
    if (idx >= BB * 2 * MSEQ) return;
    int b = idx >> 11, o = idx & 2047;
    float s = be[o];
#pragma unroll
    for (int j = 0; j < 16; j++) s += g_z[b*16 + j] * We[j*2048 + o];
    g_seq[idx] = s;
}

__global__ void dec_init(const float* __restrict__ Wc, const float* __restrict__ bc,
                         const float* __restrict__ embo)
{
    int idx = blockIdx.x * 256 + threadIdx.x;
    if (idx >= BB * MSEQ * DD) return;
    int d = idx & 511;
    int s = (idx >> 9) & 1023;
    int b = idx >> 19;
    float v = g_seq[b*2048 + s]        * Wc[d]
            + g_seq[b*2048 + 1024 + s] * Wc[512 + d]
            + bc[d] + embo[s*DD + d];
    size_t o = ((size_t)b*SPD + s) * DD + d;
    g_h[o] = v;
    g_hh[o] = __float2half_rn(v);
}

__global__ void zero_pad_rows()
{
    int idx = blockIdx.x * 256 + threadIdx.x;
    int nper = (SPD - MSEQ) * DD;
    if (idx >= BB * nper) return;
    int b = idx / nper;
    int r = idx % nper;
    size_t o = ((size_t)b*SPD + MSEQ) * DD + r;
    g_h[o] = 0.f;
    g_hh[o] = __float2half_rn(0.f);
}

__global__ void out_proj(const float* __restrict__ Ws, const float* __restrict__ bs,
                         float* __restrict__ out)
{
    int idx = blockIdx.x * 256 + threadIdx.x;
    if (idx >= BB * MSEQ * 16) return;
    int j = idx & 15;
    int s = (idx >> 4) & 1023;
    int b = idx >> 14;
    const float* hr = g_h + ((size_t)b*SPD + s) * DD;
    float acc = bs[j];
    for (int d = 0; d < DD; d++) acc += hr[d] * Ws[d*16 + j];
    out[idx] = acc;
}

__global__ void elbo_fin(float* out, int out_size)
{
    if (threadIdx.x == 0 && out_size > BB*MSEQ*16) {
        float s = 0.f;
        for (int i = 0; i < BB; i++) s += g_elbo_b[i];
        out[BB*MSEQ*16] = s * (1.f / BB);
    }
}

// ---------------- launch ----------------
extern "C" void kernel_launch(void* const* d_in, const int* in_sizes, int n_in,
                              void* d_out, int out_size)
{
    const float* x       = (const float*)d_in[0];
    const float* eps     = (const float*)d_in[1];
    const float* emb_in  = (const float*)d_in[2];
    const float* emb_out = (const float*)d_in[3];
    const float* W_data  = (const float*)d_in[4];
    const float* b_data  = (const float*)d_in[5];
    const float* Wqkv    = (const float*)d_in[6];
    const float* bqkv    = (const float*)d_in[7];
    const float* Wo      = (const float*)d_in[8];
    const float* bo      = (const float*)d_in[9];
    const float* ln1_g   = (const float*)d_in[10];
    const float* ln1_b   = (const float*)d_in[11];
    const float* W1      = (const float*)d_in[12];
    const float* b1      = (const float*)d_in[13];
    const float* W2      = (const float*)d_in[14];
    const float* b2      = (const float*)d_in[15];
    const float* ln2_g   = (const float*)d_in[16];
    const float* ln2_b   = (const float*)d_in[17];
    const float* W_mean  = (const float*)d_in[18];
    const float* b_mean  = (const float*)d_in[19];
    const float* W_lv    = (const float*)d_in[20];
    const float* b_lv    = (const float*)d_in[21];
    const float* W_exp   = (const float*)d_in[22];
    const float* b_exp   = (const float*)d_in[23];
    const float* W_conv  = (const float*)d_in[24];
    const float* b_conv  = (const float*)d_in[25];
    const float* W_seq   = (const float*)d_in[26];
    const float* b_seq   = (const float*)d_in[27];
    const int*   rand_enc= (const int*)d_in[28];
    const int*   rand_dec= (const int*)d_in[29];

    float *h_, *qkv_, *tmp_;
    __half *hh_, *atth_, *ffh_, *wb_;
    cudaGetSymbolAddress((void**)&h_,    g_h);
    cudaGetSymbolAddress((void**)&hh_,   g_hh);
    cudaGetSymbolAddress((void**)&qkv_,  g_qkv);
    cudaGetSymbolAddress((void**)&atth_, g_atth);
    cudaGetSymbolAddress((void**)&tmp_,  g_tmp);
    cudaGetSymbolAddress((void**)&ffh_,  g_ffh);
    cudaGetSymbolAddress((void**)&wb_,   g_wb);

    cudaFuncSetAttribute(gemm_tc, cudaFuncAttributeMaxDynamicSharedMemorySize, SMEM_GEMM);

    const int M = MTOT;

    // convert all weights to fp16 [N,K] once per replay
    for (int i = 0; i < 10; i++) {
        size_t L = (size_t)i * WB_PER_LAYER;
        wconv<<<dim3(1536/32, 512/32), dim3(32,8)>>>(Wqkv + (size_t)i*512*1536,
                                                     wb_ + L, 512, 1536);
        wconv<<<dim3(512/32, 512/32), dim3(32,8)>>>(Wo + (size_t)i*512*512,
                                                    wb_ + L + 786432, 512, 512);
        wconv<<<dim3(2048/32, 512/32), dim3(32,8)>>>(W1 + (size_t)i*512*2048,
                                                     wb_ + L + 1048576, 512, 2048);
        wconv<<<dim3(512/32, 2048/32), dim3(32,8)>>>(W2 + (size_t)i*2048*512,
                                                     wb_ + L + 2097152, 2048, 512);
    }

    embed_enc<<<(BB*SPD*DD + 255)/256, 256>>>(x, W_data, b_data, emb_in);

    for (int i = 0; i < 10; i++) {
        const int* rnd = (i < 5) ? rand_enc : rand_dec;
        int nb = (i < 5) ? 129 : 128;
        int S  = (i < 5) ? 1025 : 1024;
        size_t L = (size_t)i * WB_PER_LAYER;

        // qkv = h @ Wqkv + b  (fp32 out)
        gemm_tc<<<dim3(12, M/128), 256, SMEM_GEMM>>>(hh_, wb_ + L,
            bqkv + (size_t)i*1536, qkv_, 1536, 512, 0);
        attn_kernel<<<dim3(nb, HH, BB), 256>>>(qkv_, atth_, rnd, nb, S);
        // proj (fp32 out)
        gemm_tc<<<dim3(4, M/128), 256, SMEM_GEMM>>>(atth_, wb_ + L + 786432,
            bo + (size_t)i*512, tmp_, 512, 512, 0);
        add_ln<<<M, 256>>>(h_, hh_, tmp_, ln1_g + (size_t)i*DD, ln1_b + (size_t)i*DD);
        // ffn: relu(h @ W1 + b1) -> fp16 out
        gemm_tc<<<dim3(16, M/128), 256, SMEM_GEMM>>>(hh_, wb_ + L + 1048576,
            b1 + (size_t)i*FFD, ffh_, 2048, 512, 1);
        // ff @ W2 + b2 -> fp32 out
        gemm_tc<<<dim3(4, M/128), 256, SMEM_GEMM>>>(ffh_, wb_ + L + 2097152,
            b2 + (size_t)i*512, tmp_, 512, 2048, 0);
        add_ln<<<M, 256>>>(h_, hh_, tmp_, ln2_g + (size_t)i*DD, ln2_b + (size_t)i*DD);

        if (i == 4) {
            latent<<<BB, 16>>>(W_mean, b_mean, W_lv, b_lv, eps);
            seq_expand<<<(BB*2*MSEQ + 255)/256, 256>>>(W_exp, b_exp);
            dec_init<<<(BB*MSEQ*DD + 255)/256, 256>>>(W_conv, b_conv, emb_out);
            zero_pad_rows<<<(BB*(SPD-MSEQ)*DD + 255)/256, 256>>>();
        }
    }

    out_proj<<<(BB*MSEQ*16 + 255)/256, 256>>>(W_seq, b_seq, (float*)d_out);
    elbo_fin<<<1, 32>>>((float*)d_out, out_size);
}

// round 8
// speedup vs baseline: 6.2475x; 1.8111x over previous
#include <cuda_runtime.h>
#include <cuda_bf16.h>
#include <cuda_fp16.h>
#include <cstdint>
#include <cstdio>

// ---------------- constants ----------------
#define BB   32
#define DD   512
#define HH   8
#define DHH  64
#define ABB  8
#define KK   10
#define SPD  1032
#define FFD  2048
#define LATD 16
#define MSEQ 1024
#define MTOT (BB*SPD)          // 33024 = 258*128

#define WB_PER_LAYER 3145728   // qkv 786432 + wo 262144 + w1 1048576 + w2 1048576

// ---------------- scratch (device globals; no allocation) ----------------
__device__ float  g_h   [(size_t)BB*SPD*DD];
__device__ __align__(16) __half g_hh  [(size_t)BB*SPD*DD];
__device__ __align__(16) __half g_qkvh[(size_t)BB*SPD*3*DD];
__device__ __align__(16) __half g_atth[(size_t)BB*SPD*DD];
__device__ __align__(16) __half g_tmph[(size_t)BB*SPD*DD];
__device__ __align__(16) __half g_ffh [(size_t)BB*SPD*FFD];
__device__ float  g_z   [BB*LATD];
__device__ float  g_seq [BB*2*MSEQ];
__device__ float  g_elbo_b[BB];
__device__ __align__(16) __half g_wb[(size_t)10*WB_PER_LAYER];

// ---------------- helpers ----------------
#define CPA(smaddr, gptr) \
    asm volatile("cp.async.cg.shared.global [%0], [%1], 16;" :: "r"(smaddr), "l"(gptr))
#define CPC()  asm volatile("cp.async.commit_group;" ::: "memory")
#define CPW1() asm volatile("cp.async.wait_group 1;" ::: "memory")

__device__ __forceinline__ void ldsm4(uint32_t* r, uint32_t addr)
{
    asm volatile("ldmatrix.sync.aligned.m8n8.x4.shared.b16 {%0,%1,%2,%3}, [%4];"
        : "=r"(r[0]), "=r"(r[1]), "=r"(r[2]), "=r"(r[3]) : "r"(addr));
}
__device__ __forceinline__ void mma_f16(float* d, const uint32_t* a, const uint32_t* b)
{
    asm volatile("mma.sync.aligned.m16n8k16.row.col.f32.f16.f16.f32 "
        "{%0,%1,%2,%3}, {%4,%5,%6,%7}, {%8,%9}, {%0,%1,%2,%3};"
        : "+f"(d[0]), "+f"(d[1]), "+f"(d[2]), "+f"(d[3])
        : "r"(a[0]), "r"(a[1]), "r"(a[2]), "r"(a[3]), "r"(b[0]), "r"(b[1]));
}

// smem geometry for gemm (3-stage pipeline)
#define STRB   144                 // bytes per tile row (72 halves)
#define TILEB  (128*STRB)          // 18432
#define BUFB   (2*TILEB)           // 36864: A, W
#define SM_BUF 1024
#define SMEM_GEMM (SM_BUF + 3*BUFB)   // 111616

// ---------------- weight transpose to fp16: W[K,N] -> Wh[N,K] ------
__global__ void wconv(const float* __restrict__ W, __half* __restrict__ hi, int K, int N)
{
    __shared__ float t[32][33];
    int k0 = blockIdx.y * 32, n0 = blockIdx.x * 32;
    int tx = threadIdx.x, ty = threadIdx.y;   // 32 x 8
#pragma unroll
    for (int i = 0; i < 32; i += 8)
        t[ty + i][tx] = W[(size_t)(k0 + ty + i) * N + n0 + tx];
    __syncthreads();
#pragma unroll
    for (int i = 0; i < 32; i += 8)
        hi[(size_t)(n0 + ty + i) * K + k0 + tx] = __float2half_rn(t[tx][ty + i]);
}

// ---------------- tensor-core GEMM (mma.sync fp16, 3-stage pipeline) ----------
// C[M,N] = A @ W^T + bias.  A fp16 [M,Kd]; W fp16 [N,Kd].
// mode 1: fp16 out + relu.  mode 2: fp16 out.
__global__ void __launch_bounds__(256) gemm_tc(
    const __half* __restrict__ A, const __half* __restrict__ W,
    const float* __restrict__ bias, __half* __restrict__ C,
    int N, int Kd, int mode)
{
    extern __shared__ char smem[];
    const int tid = threadIdx.x;
    const int lane = tid & 31, wid = tid >> 5;
    const int wr = wid >> 2, wc = wid & 3;          // 2 x 4 warp grid
    const int m0 = blockIdx.y * 128, n0 = blockIdx.x * 128;

    uint32_t sb;
    asm("{ .reg .u64 t; cvta.to.shared.u64 t, %1; cvt.u32.u64 %0, t; }"
        : "=r"(sb) : "l"(smem));

    float* biasS = (float*)smem;
    if (tid < 128) biasS[tid] = bias[n0 + tid];

    const int CHK = Kd >> 6;

#define LOAD_TILE(dstoff, gbase)                                                 \
    {                                                                            \
        _Pragma("unroll")                                                        \
        for (int it = 0; it < 4; it++) {                                         \
            int s = it*256 + tid;                                                \
            int r = s >> 3, seg = s & 7;                                         \
            const __half* gp = (gbase) + (size_t)r * Kd + seg*8;                 \
            CPA(sb + (dstoff) + r*STRB + seg*16, gp);                            \
        }                                                                        \
    }

#define LOAD_CHUNK(buf, c)                                                       \
    {                                                                            \
        const __half* ao = A + (size_t)m0*Kd + (c)*64;                           \
        const __half* wo = W + (size_t)n0*Kd + (c)*64;                           \
        LOAD_TILE(SM_BUF + (buf)*BUFB + 0*TILEB, ao);                            \
        LOAD_TILE(SM_BUF + (buf)*BUFB + 1*TILEB, wo);                            \
        CPC();                                                                   \
    }

    LOAD_CHUNK(0, 0);
    LOAD_CHUNK(1, 1);

    float acc[4][4][4] = {};

    const uint32_t aoff = (wr*64 + (lane & 15))*STRB + (lane >> 4)*16;
    const uint32_t boff = (wc*32 + (lane >> 4)*8 + (lane & 7))*STRB + ((lane >> 3) & 1)*16;

    int cb = 0;
    for (int c = 0; c < CHK; c++) {
        CPW1();
        __syncthreads();
        if (c + 2 < CHK) {
            int nb3 = cb + 2; if (nb3 >= 3) nb3 -= 3;
            LOAD_CHUNK(nb3, c + 2);
        } else {
            CPC();
        }
        uint32_t B = sb + SM_BUF + cb*BUFB;
#pragma unroll
        for (int ks = 0; ks < 4; ks++) {
            uint32_t ka = ks*32;
            uint32_t ar[4][4], br[2][4];
#pragma unroll
            for (int i = 0; i < 4; i++)
                ldsm4(ar[i], B + 0*TILEB + aoff + i*16*STRB + ka);
#pragma unroll
            for (int g = 0; g < 2; g++)
                ldsm4(br[g], B + 1*TILEB + boff + g*16*STRB + ka);
#pragma unroll
            for (int i = 0; i < 4; i++)
#pragma unroll
            for (int j = 0; j < 4; j++)
                mma_f16(acc[i][j], ar[i], &br[j >> 1][(j & 1)*2]);
        }
        cb = (cb + 1 == 3) ? 0 : cb + 1;
    }

    // epilogue (fp16 out)
#pragma unroll
    for (int i = 0; i < 4; i++) {
        int row = m0 + wr*64 + i*16 + (lane >> 2);
#pragma unroll
        for (int j = 0; j < 4; j++) {
            int col = n0 + wc*32 + j*8 + (lane & 3)*2;
            float b0 = biasS[col - n0], b1 = biasS[col - n0 + 1];
            float v00 = acc[i][j][0] + b0, v01 = acc[i][j][1] + b1;
            float v10 = acc[i][j][2] + b0, v11 = acc[i][j][3] + b1;
            if (mode == 1) {
                v00 = fmaxf(v00, 0.f); v01 = fmaxf(v01, 0.f);
                v10 = fmaxf(v10, 0.f); v11 = fmaxf(v11, 0.f);
            }
            *(__half2*)&C[(size_t)row * N + col]       = __floats2half2_rn(v00, v01);
            *(__half2*)&C[(size_t)(row + 8) * N + col] = __floats2half2_rn(v10, v11);
        }
    }
#undef LOAD_TILE
#undef LOAD_CHUNK
}

// ---------------- encoder embedding (writes h fp32 + fp16) ----------------
__global__ void embed_enc(const float* __restrict__ x, const float* __restrict__ Wd,
                          const float* __restrict__ bd, const float* __restrict__ emb)
{
    int idx = blockIdx.x * blockDim.x + threadIdx.x;
    if (idx >= BB*SPD*DD) return;
    int d = idx & 511;
    int s = (idx >> 9) % SPD;
    int b = idx / (SPD*DD);
    float v = 0.f;
    if (s < MSEQ + 1) {
        v = emb[s*DD + d];
        if (s > 0) {
            const float* xr = x + ((size_t)b*MSEQ + (s-1)) * 16;
            float acc = bd[d];
#pragma unroll
            for (int j = 0; j < 16; j++) acc += xr[j] * Wd[j*DD + d];
            v += acc;
        }
    }
    g_h[idx] = v;
    g_hh[idx] = __float2half_rn(v);
}

// ---------------- block-sparse attention (fp16 in/out, fp32 accumulate) -------
// smem rows padded to 34 half2 (136 B, 8B-aligned) for uint2 vector access.
__global__ void attn_kernel(const __half* __restrict__ qkv, __half* __restrict__ out,
                            const int* __restrict__ rnd, int nb, int S)
{
    int n = blockIdx.x, h = blockIdx.y, b = blockIdx.z;
    int tid = threadIdx.x;

    __shared__ __half2 qs[8][34];
    __shared__ __half2 ks[80][34];
    __shared__ __half2 vs[80][34];
    __shared__ float sc[8][80];
    __shared__ int   sbidx[KK];
    __shared__ int   svalid[KK];
    __shared__ float kmaskadd[80];

    if (tid < KK) {
        int j = tid, idx, valid = 1;
        if (j < 2)       { idx = j; }
        else if (j < 7)  { int w = n + j - 4; valid = (w >= 0 && w < nb);
                           idx = min(max(w, 0), nb - 1); }
        else             { idx = rnd[n*3 + (j - 7)]; }
        sbidx[j]  = idx;
        svalid[j] = valid;
    }
    __syncthreads();
    if (tid < 80) {
        int j = tid >> 3, p = tid & 7;
        int tok = sbidx[j]*ABB + p;
        kmaskadd[tid] = (svalid[j] && tok < S) ? 0.f : -1e9f;
    }

    const __half* base = qkv + (size_t)b * SPD * (3*DD);
    // Q: 8 rows x 16 uint2 (4 halves each)
    if (tid < 128) {
        int p = tid >> 4, seg = tid & 15;
        uint2 v = *(const uint2*)(base + (size_t)(n*ABB + p)*(3*DD) + h*DHH + seg*4);
        *(uint2*)&qs[p][seg*2] = v;
    }
    // K/V: 80 rows x 16 uint2 each
    for (int e = tid; e < 80*16; e += 256) {
        int kk = e >> 4, seg = e & 15;
        int j = kk >> 3, p = kk & 7;
        int row = sbidx[j]*ABB + p;
        const __half* rp = base + (size_t)row*(3*DD) + h*DHH + seg*4;
        *(uint2*)&ks[kk][seg*2] = *(const uint2*)(rp + DD);
        *(uint2*)&vs[kk][seg*2] = *(const uint2*)(rp + 2*DD);
    }
    __syncthreads();

    for (int e = tid; e < 640; e += 256) {
        int qi = e / 80, kk = e % 80;
        float s = 0.f;
#pragma unroll
        for (int d2 = 0; d2 < 32; d2++) {
            float2 a = __half22float2(qs[qi][d2]);
            float2 bb = __half22float2(ks[kk][d2]);
            s += a.x*bb.x + a.y*bb.y;
        }
        sc[qi][kk] = s * 0.125f + kmaskadd[kk];
    }
    __syncthreads();

    int warp = tid >> 5, lane = tid & 31;
    if (warp < 8) {
        float v0 = sc[warp][lane];
        float v1 = sc[warp][lane + 32];
        float v2 = (lane < 16) ? sc[warp][lane + 64] : -1e30f;
        float m = fmaxf(fmaxf(v0, v1), v2);
        for (int o = 16; o; o >>= 1) m = fmaxf(m, __shfl_xor_sync(~0u, m, o));
        float e0 = __expf(v0 - m), e1 = __expf(v1 - m);
        float e2 = (lane < 16) ? __expf(v2 - m) : 0.f;
        float s = e0 + e1 + e2;
        for (int o = 16; o; o >>= 1) s += __shfl_xor_sync(~0u, s, o);
        float inv = 1.f / s;
        sc[warp][lane]      = e0 * inv;
        sc[warp][lane + 32] = e1 * inv;
        if (lane < 16) sc[warp][lane + 64] = e2 * inv;
    }
    __syncthreads();

    for (int e = tid; e < 8*32; e += 256) {
        int qi = e >> 5, d2 = e & 31;
        float ax = 0.f, ay = 0.f;
#pragma unroll
        for (int kk = 0; kk < 80; kk++) {
            float s = sc[qi][kk];
            float2 v = __half22float2(vs[kk][d2]);
            ax += s * v.x; ay += s * v.y;
        }
        *(__half2*)&out[((size_t)b*SPD + n*ABB + qi) * DD + h*DHH + d2*2] =
            __floats2half2_rn(ax, ay);
    }
}

// ---------------- fused residual add (half) + LayerNorm (fp32+fp16 out) ------
__global__ void add_ln(float* __restrict__ h, __half* __restrict__ hh,
                       const __half* __restrict__ a,
                       const float* __restrict__ g, const float* __restrict__ be)
{
    int row = blockIdx.x;
    int tid = threadIdx.x;          // 256
    float* hr = h + (size_t)row * DD;
    __half* hhr = hh + (size_t)row * DD;
    const __half* ar = a + (size_t)row * DD;
    float x0 = hr[tid]       + __half2float(ar[tid]);
    float x1 = hr[tid + 256] + __half2float(ar[tid + 256]);
    float s = x0 + x1, q = x0*x0 + x1*x1;
    for (int o = 16; o; o >>= 1) {
        s += __shfl_xor_sync(~0u, s, o);
        q += __shfl_xor_sync(~0u, q, o);
    }
    __shared__ float ss[8], sq[8];
    int w = tid >> 5, l = tid & 31;
    if (l == 0) { ss[w] = s; sq[w] = q; }
    __syncthreads();
    if (tid == 0) {
        float S = 0, Q = 0;
        for (int i = 0; i < 8; i++) { S += ss[i]; Q += sq[i]; }
        ss[0] = S * (1.f/512.f);
        sq[0] = Q * (1.f/512.f);
    }
    __syncthreads();
    float m = ss[0];
    float inv = rsqrtf(sq[0] - m*m + 1e-5f);
    float y0 = (x0 - m) * inv * g[tid]       + be[tid];
    float y1 = (x1 - m) * inv * g[tid + 256] + be[tid + 256];
    hr[tid]        = y0;
    hr[tid + 256]  = y1;
    hhr[tid]       = __float2half_rn(y0);
    hhr[tid + 256] = __float2half_rn(y1);
}

// ---------------- latent head ----------
__global__ void latent(const float* __restrict__ Wm, const float* __restrict__ bm,
                       const float* __restrict__ Wl, const float* __restrict__ bl,
                       const float* __restrict__ eps)
{
    int b = blockIdx.x, t = threadIdx.x;   // 16 threads
    const float* p = g_h + (size_t)b * SPD * DD;
    float m = bm[t], l = bl[t];
    for (int d = 0; d < DD; d++) {
        float pv = p[d];
        m += pv * Wm[d*LATD + t];
        l += pv * Wl[d*LATD + t];
    }
    g_z[b*LATD + t] = m + eps[b*LATD + t] * __expf(0.5f * l);
    float c = 1.f + l - m*m - __expf(l);
    for (int o = 8; o; o >>= 1) c += __shfl_xor_sync(0xffffu, c, o, 16);
    if (t == 0) g_elbo_b[b] = -0.5f * c;
}

__global__ void seq_expand(const float* __restrict__ We, const float* __restrict__ be)
{
    int idx = blockIdx.x * 256 + threadIdx.x;
    if (idx >= BB * 2 * MSEQ) return;
    int b = idx >> 11, o = idx & 2047;
    float s = be[o];
#pragma unroll
    for (int j = 0; j < 16; j++) s += g_z[b*16 + j] * We[j*2048 + o];
    g_seq[idx] = s;
}

__global__ void dec_init(const float* __restrict__ Wc, const float* __restrict__ bc,
                         const float* __restrict__ embo)
{
    int idx = blockIdx.x * 256 + threadIdx.x;
    if (idx >= BB * MSEQ * DD) return;
    int d = idx & 511;
    int s = (idx >> 9) & 1023;
    int b = idx >> 19;
    float v = g_seq[b*2048 + s]        * Wc[d]
            + g_seq[b*2048 + 1024 + s] * Wc[512 + d]
            + bc[d] + embo[s*DD + d];
    size_t o = ((size_t)b*SPD + s) * DD + d;
    g_h[o] = v;
    g_hh[o] = __float2half_rn(v);
}

__global__ void zero_pad_rows()
{
    int idx = blockIdx.x * 256 + threadIdx.x;
    int nper = (SPD - MSEQ) * DD;
    if (idx >= BB * nper) return;
    int b = idx / nper;
    int r = idx % nper;
    size_t o = ((size_t)b*SPD + MSEQ) * DD + r;
    g_h[o] = 0.f;
    g_hh[o] = __float2half_rn(0.f);
}

__global__ void out_proj(const float* __restrict__ Ws, const float* __restrict__ bs,
                         float* __restrict__ out)
{
    int idx = blockIdx.x * 256 + threadIdx.x;
    if (idx >= BB * MSEQ * 16) return;
    int j = idx & 15;
    int s = (idx >> 4) & 1023;
    int b = idx >> 14;
    const float* hr = g_h + ((size_t)b*SPD + s) * DD;
    float acc = bs[j];
    for (int d = 0; d < DD; d++) acc += hr[d] * Ws[d*16 + j];
    out[idx] = acc;
}

__global__ void elbo_fin(float* out, int out_size)
{
    if (threadIdx.x == 0 && out_size > BB*MSEQ*16) {
        float s = 0.f;
        for (int i = 0; i < BB; i++) s += g_elbo_b[i];
        out[BB*MSEQ*16] = s * (1.f / BB);
    }
}

// ---------------- launch ----------------
extern "C" void kernel_launch(void* const* d_in, const int* in_sizes, int n_in,
                              void* d_out, int out_size)
{
    const float* x       = (const float*)d_in[0];
    const float* eps     = (const float*)d_in[1];
    const float* emb_in  = (const float*)d_in[2];
    const float* emb_out = (const float*)d_in[3];
    const float* W_data  = (const float*)d_in[4];
    const float* b_data  = (const float*)d_in[5];
    const float* Wqkv    = (const float*)d_in[6];
    const float* bqkv    = (const float*)d_in[7];
    const float* Wo      = (const float*)d_in[8];
    const float* bo      = (const float*)d_in[9];
    const float* ln1_g   = (const float*)d_in[10];
    const float* ln1_b   = (const float*)d_in[11];
    const float* W1      = (const float*)d_in[12];
    const float* b1      = (const float*)d_in[13];
    const float* W2      = (const float*)d_in[14];
    const float* b2      = (const float*)d_in[15];
    const float* ln2_g   = (const float*)d_in[16];
    const float* ln2_b   = (const float*)d_in[17];
    const float* W_mean  = (const float*)d_in[18];
    const float* b_mean  = (const float*)d_in[19];
    const float* W_lv    = (const float*)d_in[20];
    const float* b_lv    = (const float*)d_in[21];
    const float* W_exp   = (const float*)d_in[22];
    const float* b_exp   = (const float*)d_in[23];
    const float* W_conv  = (const float*)d_in[24];
    const float* b_conv  = (const float*)d_in[25];
    const float* W_seq   = (const float*)d_in[26];
    const float* b_seq   = (const float*)d_in[27];
    const int*   rand_enc= (const int*)d_in[28];
    const int*   rand_dec= (const int*)d_in[29];

    float *h_;
    __half *hh_, *qkvh_, *atth_, *tmph_, *ffh_, *wb_;
    cudaGetSymbolAddress((void**)&h_,    g_h);
    cudaGetSymbolAddress((void**)&hh_,   g_hh);
    cudaGetSymbolAddress((void**)&qkvh_, g_qkvh);
    cudaGetSymbolAddress((void**)&atth_, g_atth);
    cudaGetSymbolAddress((void**)&tmph_, g_tmph);
    cudaGetSymbolAddress((void**)&ffh_,  g_ffh);
    cudaGetSymbolAddress((void**)&wb_,   g_wb);

    cudaFuncSetAttribute(gemm_tc, cudaFuncAttributeMaxDynamicSharedMemorySize, SMEM_GEMM);

    const int M = MTOT;

    // convert all weights to fp16 [N,K] once per replay
    for (int i = 0; i < 10; i++) {
        size_t L = (size_t)i * WB_PER_LAYER;
        wconv<<<dim3(1536/32, 512/32), dim3(32,8)>>>(Wqkv + (size_t)i*512*1536,
                                                     wb_ + L, 512, 1536);
        wconv<<<dim3(512/32, 512/32), dim3(32,8)>>>(Wo + (size_t)i*512*512,
                                                    wb_ + L + 786432, 512, 512);
        wconv<<<dim3(2048/32, 512/32), dim3(32,8)>>>(W1 + (size_t)i*512*2048,
                                                     wb_ + L + 1048576, 512, 2048);
        wconv<<<dim3(512/32, 2048/32), dim3(32,8)>>>(W2 + (size_t)i*2048*512,
                                                     wb_ + L + 2097152, 2048, 512);
    }

    embed_enc<<<(BB*SPD*DD + 255)/256, 256>>>(x, W_data, b_data, emb_in);

    for (int i = 0; i < 10; i++) {
        const int* rnd = (i < 5) ? rand_enc : rand_dec;
        int nb = (i < 5) ? 129 : 128;
        int S  = (i < 5) ? 1025 : 1024;
        size_t L = (size_t)i * WB_PER_LAYER;

        // qkv = h @ Wqkv + b  (fp16 out)
        gemm_tc<<<dim3(12, M/128), 256, SMEM_GEMM>>>(hh_, wb_ + L,
            bqkv + (size_t)i*1536, qkvh_, 1536, 512, 2);
        attn_kernel<<<dim3(nb, HH, BB), 256>>>(qkvh_, atth_, rnd, nb, S);
        // proj (fp16 out)
        gemm_tc<<<dim3(4, M/128), 256, SMEM_GEMM>>>(atth_, wb_ + L + 786432,
            bo + (size_t)i*512, tmph_, 512, 512, 2);
        add_ln<<<M, 256>>>(h_, hh_, tmph_, ln1_g + (size_t)i*DD, ln1_b + (size_t)i*DD);
        // ffn: relu(h @ W1 + b1) -> fp16
        gemm_tc<<<dim3(16, M/128), 256, SMEM_GEMM>>>(hh_, wb_ + L + 1048576,
            b1 + (size_t)i*FFD, ffh_, 2048, 512, 1);
        // ff @ W2 + b2 -> fp16
        gemm_tc<<<dim3(4, M/128), 256, SMEM_GEMM>>>(ffh_, wb_ + L + 2097152,
            b2 + (size_t)i*512, tmph_, 512, 2048, 2);
        add_ln<<<M, 256>>>(h_, hh_, tmph_, ln2_g + (size_t)i*DD, ln2_b + (size_t)i*DD);

        if (i == 4) {
            latent<<<BB, 16>>>(W_mean, b_mean, W_lv, b_lv, eps);
            seq_expand<<<(BB*2*MSEQ + 255)/256, 256>>>(W_exp, b_exp);
            dec_init<<<(BB*MSEQ*DD + 255)/256, 256>>>(W_conv, b_conv, emb_out);
            zero_pad_rows<<<(BB*(SPD-MSEQ)*DD + 255)/256, 256>>>();
        }
    }

    out_proj<<<(BB*MSEQ*16 + 255)/256, 256>>>(W_seq, b_seq, (float*)d_out);
    elbo_fin<<<1, 32>>>((float*)d_out, out_size);
}

// round 10
// speedup vs baseline: 6.8740x; 1.1003x over previous
#include <cuda_runtime.h>
#include <cuda_bf16.h>
#include <cuda_fp16.h>
#include <cstdint>
#include <cstdio>

// ---------------- constants ----------------
#define BB   32
#define DD   512
#define HH   8
#define DHH  64
#define ABB  8
#define KK   10
#define SPD  1032
#define FFD  2048
#define LATD 16
#define MSEQ 1024
#define MTOT (BB*SPD)          // 33024 = 258*128

#define WB_PER_LAYER 3145728   // qkv 786432 + wo 262144 + w1 1048576 + w2 1048576

// ---------------- scratch (device globals; no allocation) ----------------
__device__ float  g_h   [(size_t)BB*SPD*DD];
__device__ __align__(16) __half g_hh  [(size_t)BB*SPD*DD];
__device__ __align__(16) __half g_qkvh[(size_t)BB*SPD*3*DD];
__device__ __align__(16) __half g_atth[(size_t)BB*SPD*DD];
__device__ __align__(16) __half g_tmph[(size_t)BB*SPD*DD];
__device__ __align__(16) __half g_ffh [(size_t)BB*SPD*FFD];
__device__ float  g_z   [BB*LATD];
__device__ float  g_seq [BB*2*MSEQ];
__device__ float  g_elbo_b[BB];
__device__ __align__(16) __half g_wb[(size_t)10*WB_PER_LAYER];

// ---------------- helpers ----------------
#define CPA(smaddr, gptr) \
    asm volatile("cp.async.cg.shared.global [%0], [%1], 16;" :: "r"(smaddr), "l"(gptr))
#define CPC()  asm volatile("cp.async.commit_group;" ::: "memory")
#define CPW1() asm volatile("cp.async.wait_group 1;" ::: "memory")

__device__ __forceinline__ void ldsm4(uint32_t* r, uint32_t addr)
{
    asm volatile("ldmatrix.sync.aligned.m8n8.x4.shared.b16 {%0,%1,%2,%3}, [%4];"
        : "=r"(r[0]), "=r"(r[1]), "=r"(r[2]), "=r"(r[3]) : "r"(addr));
}
__device__ __forceinline__ void mma_f16(float* d, const uint32_t* a, const uint32_t* b)
{
    asm volatile("mma.sync.aligned.m16n8k16.row.col.f32.f16.f16.f32 "
        "{%0,%1,%2,%3}, {%4,%5,%6,%7}, {%8,%9}, {%0,%1,%2,%3};"
        : "+f"(d[0]), "+f"(d[1]), "+f"(d[2]), "+f"(d[3])
        : "r"(a[0]), "r"(a[1]), "r"(a[2]), "r"(a[3]), "r"(b[0]), "r"(b[1]));
}

// smem geometry for gemm: XOR-swizzled 128B rows, 3-stage pipeline
#define TILEB  (128*128)            // 16384: 128 rows x 64 halves
#define BUFB   (2*TILEB)            // 32768: A, W
#define SM_BUF 1024
#define SMEM_GEMM (SM_BUF + 3*BUFB) // 99328

// ---------------- weight transpose to fp16: W[K,N] -> Wh[N,K], batched -------
__global__ void wconv(const float* __restrict__ W, __half* __restrict__ hi,
                      int K, int N, size_t win_str, size_t wout_str)
{
    __shared__ float t[32][33];
    const float* Wl = W + (size_t)blockIdx.z * win_str;
    __half* hl = hi + (size_t)blockIdx.z * wout_str;
    int k0 = blockIdx.y * 32, n0 = blockIdx.x * 32;
    int tx = threadIdx.x, ty = threadIdx.y;   // 32 x 8
#pragma unroll
    for (int i = 0; i < 32; i += 8)
        t[ty + i][tx] = Wl[(size_t)(k0 + ty + i) * N + n0 + tx];
    __syncthreads();
#pragma unroll
    for (int i = 0; i < 32; i += 8)
        hl[(size_t)(n0 + ty + i) * K + k0 + tx] = __float2half_rn(t[tx][ty + i]);
}

// ---------------- tensor-core GEMM (mma.sync fp16, swizzled, 3-stage) ---------
// C[M,N] = A @ W^T + bias.  A fp16 [M,Kd]; W fp16 [N,Kd].
// mode 1: fp16 out + relu.  mode 2: fp16 out.
__global__ void __launch_bounds__(256) gemm_tc(
    const __half* __restrict__ A, const __half* __restrict__ W,
    const float* __restrict__ bias, __half* __restrict__ C,
    int N, int Kd, int mode)
{
    extern __shared__ char smem[];
    const int tid = threadIdx.x;
    const int lane = tid & 31, wid = tid >> 5;
    const int wr = wid >> 2, wc = wid & 3;          // 2 x 4 warp grid
    const int m0 = blockIdx.y * 128, n0 = blockIdx.x * 128;

    uint32_t sb;
    asm("{ .reg .u64 t; cvta.to.shared.u64 t, %1; cvt.u32.u64 %0, t; }"
        : "=r"(sb) : "l"(smem));

    float* biasS = (float*)smem;
    if (tid < 128) biasS[tid] = bias[n0 + tid];

    const int CHK = Kd >> 6;

    // swizzled cp.async loader: row r (128B), nominal seg s -> seg s^(r&7)
#define LOAD_TILE(dstoff, gbase)                                                 \
    {                                                                            \
        _Pragma("unroll")                                                        \
        for (int it = 0; it < 4; it++) {                                         \
            int s = it*256 + tid;                                                \
            int r = s >> 3, seg = s & 7;                                         \
            const __half* gp = (gbase) + (size_t)r * Kd + seg*8;                 \
            CPA(sb + (dstoff) + r*128 + ((seg ^ (r & 7)) << 4), gp);             \
        }                                                                        \
    }

#define LOAD_CHUNK(buf, c)                                                       \
    {                                                                            \
        const __half* ao = A + (size_t)m0*Kd + (c)*64;                           \
        const __half* wo = W + (size_t)n0*Kd + (c)*64;                           \
        LOAD_TILE(SM_BUF + (buf)*BUFB + 0*TILEB, ao);                            \
        LOAD_TILE(SM_BUF + (buf)*BUFB + 1*TILEB, wo);                            \
        CPC();                                                                   \
    }

    LOAD_CHUNK(0, 0);
    LOAD_CHUNK(1, 1);

    float acc[4][4][4] = {};

    // per-lane fragment rows + swizzle keys
    uint32_t arow[4], akey[4];
#pragma unroll
    for (int i = 0; i < 4; i++) {
        uint32_t ra = wr*64 + i*16 + (lane & 15);
        arow[i] = ra * 128;
        akey[i] = ra & 7;
    }
    const uint32_t ahi = lane >> 4;            // 0/1: nominal 16B seg within k16
    uint32_t brow[2], bkey[2];
#pragma unroll
    for (int g = 0; g < 2; g++) {
        uint32_t rb = wc*32 + g*16 + (lane >> 4)*8 + (lane & 7);
        brow[g] = rb * 128;
        bkey[g] = rb & 7;
    }
    const uint32_t bhi = (lane >> 3) & 1;

    int cb = 0;
    for (int c = 0; c < CHK; c++) {
        CPW1();
        __syncthreads();
        if (c + 2 < CHK) {
            int nb3 = cb + 2; if (nb3 >= 3) nb3 -= 3;
            LOAD_CHUNK(nb3, c + 2);
        } else {
            CPC();
        }
        uint32_t Bs = sb + SM_BUF + cb*BUFB;
#pragma unroll
        for (int ks = 0; ks < 4; ks++) {
            uint32_t ca = ks*2 + ahi;
            uint32_t cbn = ks*2 + bhi;
            uint32_t ar[4][4], br[2][4];
#pragma unroll
            for (int i = 0; i < 4; i++)
                ldsm4(ar[i], Bs + arow[i] + (((ca ^ akey[i])) << 4));
#pragma unroll
            for (int g = 0; g < 2; g++)
                ldsm4(br[g], Bs + TILEB + brow[g] + (((cbn ^ bkey[g])) << 4));
#pragma unroll
            for (int i = 0; i < 4; i++)
#pragma unroll
            for (int j = 0; j < 4; j++)
                mma_f16(acc[i][j], ar[i], &br[j >> 1][(j & 1)*2]);
        }
        cb = (cb + 1 == 3) ? 0 : cb + 1;
    }

    // epilogue (fp16 out)
#pragma unroll
    for (int i = 0; i < 4; i++) {
        int row = m0 + wr*64 + i*16 + (lane >> 2);
#pragma unroll
        for (int j = 0; j < 4; j++) {
            int col = n0 + wc*32 + j*8 + (lane & 3)*2;
            float b0 = biasS[col - n0], b1 = biasS[col - n0 + 1];
            float v00 = acc[i][j][0] + b0, v01 = acc[i][j][1] + b1;
            float v10 = acc[i][j][2] + b0, v11 = acc[i][j][3] + b1;
            if (mode == 1) {
                v00 = fmaxf(v00, 0.f); v01 = fmaxf(v01, 0.f);
                v10 = fmaxf(v10, 0.f); v11 = fmaxf(v11, 0.f);
            }
            *(__half2*)&C[(size_t)row * N + col]       = __floats2half2_rn(v00, v01);
            *(__half2*)&C[(size_t)(row + 8) * N + col] = __floats2half2_rn(v10, v11);
        }
    }
#undef LOAD_TILE
#undef LOAD_CHUNK
}

// ---------------- encoder embedding (writes h fp32 + fp16) ----------------
__global__ void embed_enc(const float* __restrict__ x, const float* __restrict__ Wd,
                          const float* __restrict__ bd, const float* __restrict__ emb)
{
    int idx = blockIdx.x * blockDim.x + threadIdx.x;
    if (idx >= BB*SPD*DD) return;
    int d = idx & 511;
    int s = (idx >> 9) % SPD;
    int b = idx / (SPD*DD);
    float v = 0.f;
    if (s < MSEQ + 1) {
        v = emb[s*DD + d];
        if (s > 0) {
            const float* xr = x + ((size_t)b*MSEQ + (s-1)) * 16;
            float acc = bd[d];
#pragma unroll
            for (int j = 0; j < 16; j++) acc += xr[j] * Wd[j*DD + d];
            v += acc;
        }
    }
    g_h[idx] = v;
    g_hh[idx] = __float2half_rn(v);
}

// ---------------- block-sparse attention (fp16 in/out, fp32 accumulate) -------
__global__ void attn_kernel(const __half* __restrict__ qkv, __half* __restrict__ out,
                            const int* __restrict__ rnd, int nb, int S)
{
    int n = blockIdx.x, h = blockIdx.y, b = blockIdx.z;
    int tid = threadIdx.x;

    __shared__ __half2 qs[8][34];
    __shared__ __half2 ks[80][34];
    __shared__ __half2 vs[80][34];
    __shared__ float sc[8][80];
    __shared__ int   sbidx[KK];
    __shared__ int   svalid[KK];
    __shared__ float kmaskadd[80];

    if (tid < KK) {
        int j = tid, idx, valid = 1;
        if (j < 2)       { idx = j; }
        else if (j < 7)  { int w = n + j - 4; valid = (w >= 0 && w < nb);
                           idx = min(max(w, 0), nb - 1); }
        else             { idx = rnd[n*3 + (j - 7)]; }
        sbidx[j]  = idx;
        svalid[j] = valid;
    }
    __syncthreads();
    if (tid < 80) {
        int j = tid >> 3, p = tid & 7;
        int tok = sbidx[j]*ABB + p;
        kmaskadd[tid] = (svalid[j] && tok < S) ? 0.f : -1e9f;
    }

    const __half* base = qkv + (size_t)b * SPD * (3*DD);
    if (tid < 128) {
        int p = tid >> 4, seg = tid & 15;
        uint2 v = *(const uint2*)(base + (size_t)(n*ABB + p)*(3*DD) + h*DHH + seg*4);
        *(uint2*)&qs[p][seg*2] = v;
    }
    for (int e = tid; e < 80*16; e += 256) {
        int kk = e >> 4, seg = e & 15;
        int j = kk >> 3, p = kk & 7;
        int row = sbidx[j]*ABB + p;
        const __half* rp = base + (size_t)row*(3*DD) + h*DHH + seg*4;
        *(uint2*)&ks[kk][seg*2] = *(const uint2*)(rp + DD);
        *(uint2*)&vs[kk][seg*2] = *(const uint2*)(rp + 2*DD);
    }
    __syncthreads();

    for (int e = tid; e < 640; e += 256) {
        int qi = e / 80, kk = e % 80;
        float s = 0.f;
#pragma unroll
        for (int d2 = 0; d2 < 32; d2++) {
            float2 a = __half22float2(qs[qi][d2]);
            float2 bb = __half22float2(ks[kk][d2]);
            s += a.x*bb.x + a.y*bb.y;
        }
        sc[qi][kk] = s * 0.125f + kmaskadd[kk];
    }
    __syncthreads();

    int warp = tid >> 5, lane = tid & 31;
    if (warp < 8) {
        float v0 = sc[warp][lane];
        float v1 = sc[warp][lane + 32];
        float v2 = (lane < 16) ? sc[warp][lane + 64] : -1e30f;
        float m = fmaxf(fmaxf(v0, v1), v2);
        for (int o = 16; o; o >>= 1) m = fmaxf(m, __shfl_xor_sync(~0u, m, o));
        float e0 = __expf(v0 - m), e1 = __expf(v1 - m);
        float e2 = (lane < 16) ? __expf(v2 - m) : 0.f;
        float s = e0 + e1 + e2;
        for (int o = 16; o; o >>= 1) s += __shfl_xor_sync(~0u, s, o);
        float inv = 1.f / s;
        sc[warp][lane]      = e0 * inv;
        sc[warp][lane + 32] = e1 * inv;
        if (lane < 16) sc[warp][lane + 64] = e2 * inv;
    }
    __syncthreads();

    for (int e = tid; e < 8*32; e += 256) {
        int qi = e >> 5, d2 = e & 31;
        float ax = 0.f, ay = 0.f;
#pragma unroll
        for (int kk = 0; kk < 80; kk++) {
            float s = sc[qi][kk];
            float2 v = __half22float2(vs[kk][d2]);
            ax += s * v.x; ay += s * v.y;
        }
        *(__half2*)&out[((size_t)b*SPD + n*ABB + qi) * DD + h*DHH + d2*2] =
            __floats2half2_rn(ax, ay);
    }
}

// ---------------- fused residual add (half) + LayerNorm (fp32+fp16 out) ------
__global__ void add_ln(float* __restrict__ h, __half* __restrict__ hh,
                       const __half* __restrict__ a,
                       const float* __restrict__ g, const float* __restrict__ be)
{
    int row = blockIdx.x;
    int tid = threadIdx.x;          // 256
    float* hr = h + (size_t)row * DD;
    __half* hhr = hh + (size_t)row * DD;
    const __half* ar = a + (size_t)row * DD;
    float x0 = hr[tid]       + __half2float(ar[tid]);
    float x1 = hr[tid + 256] + __half2float(ar[tid + 256]);
    float s = x0 + x1, q = x0*x0 + x1*x1;
    for (int o = 16; o; o >>= 1) {
        s += __shfl_xor_sync(~0u, s, o);
        q += __shfl_xor_sync(~0u, q, o);
    }
    __shared__ float ss[8], sq[8];
    int w = tid >> 5, l = tid & 31;
    if (l == 0) { ss[w] = s; sq[w] = q; }
    __syncthreads();
    if (tid == 0) {
        float S = 0, Q = 0;
        for (int i = 0; i < 8; i++) { S += ss[i]; Q += sq[i]; }
        ss[0] = S * (1.f/512.f);
        sq[0] = Q * (1.f/512.f);
    }
    __syncthreads();
    float m = ss[0];
    float inv = rsqrtf(sq[0] - m*m + 1e-5f);
    float y0 = (x0 - m) * inv * g[tid]       + be[tid];
    float y1 = (x1 - m) * inv * g[tid + 256] + be[tid + 256];
    hr[tid]        = y0;
    hr[tid + 256]  = y1;
    hhr[tid]       = __float2half_rn(y0);
    hhr[tid + 256] = __float2half_rn(y1);
}

// ---------------- latent head ----------
__global__ void latent(const float* __restrict__ Wm, const float* __restrict__ bm,
                       const float* __restrict__ Wl, const float* __restrict__ bl,
                       const float* __restrict__ eps)
{
    int b = blockIdx.x, t = threadIdx.x;   // 16 threads
    const float* p = g_h + (size_t)b * SPD * DD;
    float m = bm[t], l = bl[t];
    for (int d = 0; d < DD; d++) {
        float pv = p[d];
        m += pv * Wm[d*LATD + t];
        l += pv * Wl[d*LATD + t];
    }
    g_z[b*LATD + t] = m + eps[b*LATD + t] * __expf(0.5f * l);
    float c = 1.f + l - m*m - __expf(l);
    for (int o = 8; o; o >>= 1) c += __shfl_xor_sync(0xffffu, c, o, 16);
    if (t == 0) g_elbo_b[b] = -0.5f * c;
}

__global__ void seq_expand(const float* __restrict__ We, const float* __restrict__ be)
{
    int idx = blockIdx.x * 256 + threadIdx.x;
    if (idx >= BB * 2 * MSEQ) return;
    int b = idx >> 11, o = idx & 2047;
    float s = be[o];
#pragma unroll
    for (int j = 0; j < 16; j++) s += g_z[b*16 + j] * We[j*2048 + o];
    g_seq[idx] = s;
}

__global__ void dec_init(const float* __restrict__ Wc, const float* __restrict__ bc,
                         const float* __restrict__ embo)
{
    int idx = blockIdx.x * 256 + threadIdx.x;
    if (idx >= BB * MSEQ * DD) return;
    int d = idx & 511;
    int s = (idx >> 9) & 1023;
    int b = idx >> 19;
    float v = g_seq[b*2048 + s]        * Wc[d]
            + g_seq[b*2048 + 1024 + s] * Wc[512 + d]
            + bc[d] + embo[s*DD + d];
    size_t o = ((size_t)b*SPD + s) * DD + d;
    g_h[o] = v;
    g_hh[o] = __float2half_rn(v);
}

__global__ void zero_pad_rows()
{
    int idx = blockIdx.x * 256 + threadIdx.x;
    int nper = (SPD - MSEQ) * DD;
    if (idx >= BB * nper) return;
    int b = idx / nper;
    int r = idx % nper;
    size_t o = ((size_t)b*SPD + MSEQ) * DD + r;
    g_h[o] = 0.f;
    g_hh[o] = __float2half_rn(0.f);
}

__global__ void out_proj(const float* __restrict__ Ws, const float* __restrict__ bs,
                         float* __restrict__ out)
{
    int idx = blockIdx.x * 256 + threadIdx.x;
    if (idx >= BB * MSEQ * 16) return;
    int j = idx & 15;
    int s = (idx >> 4) & 1023;
    int b = idx >> 14;
    const float* hr = g_h + ((size_t)b*SPD + s) * DD;
    float acc = bs[j];
    for (int d = 0; d < DD; d++) acc += hr[d] * Ws[d*16 + j];
    out[idx] = acc;
}

__global__ void elbo_fin(float* out, int out_size)
{
    if (threadIdx.x == 0 && out_size > BB*MSEQ*16) {
        float s = 0.f;
        for (int i = 0; i < BB; i++) s += g_elbo_b[i];
        out[BB*MSEQ*16] = s * (1.f / BB);
    }
}

// ---------------- launch ----------------
extern "C" void kernel_launch(void* const* d_in, const int* in_sizes, int n_in,
                              void* d_out, int out_size)
{
    const float* x       = (const float*)d_in[0];
    const float* eps     = (const float*)d_in[1];
    const float* emb_in  = (const float*)d_in[2];
    const float* emb_out = (const float*)d_in[3];
    const float* W_data  = (const float*)d_in[4];
    const float* b_data  = (const float*)d_in[5];
    const float* Wqkv    = (const float*)d_in[6];
    const float* bqkv    = (const float*)d_in[7];
    const float* Wo      = (const float*)d_in[8];
    const float* bo      = (const float*)d_in[9];
    const float* ln1_g   = (const float*)d_in[10];
    const float* ln1_b   = (const float*)d_in[11];
    const float* W1      = (const float*)d_in[12];
    const float* b1      = (const float*)d_in[13];
    const float* W2      = (const float*)d_in[14];
    const float* b2      = (const float*)d_in[15];
    const float* ln2_g   = (const float*)d_in[16];
    const float* ln2_b   = (const float*)d_in[17];
    const float* W_mean  = (const float*)d_in[18];
    const float* b_mean  = (const float*)d_in[19];
    const float* W_lv    = (const float*)d_in[20];
    const float* b_lv    = (const float*)d_in[21];
    const float* W_exp   = (const float*)d_in[22];
    const float* b_exp   = (const float*)d_in[23];
    const float* W_conv  = (const float*)d_in[24];
    const float* b_conv  = (const float*)d_in[25];
    const float* W_seq   = (const float*)d_in[26];
    const float* b_seq   = (const float*)d_in[27];
    const int*   rand_enc= (const int*)d_in[28];
    const int*   rand_dec= (const int*)d_in[29];

    float *h_;
    __half *hh_, *qkvh_, *atth_, *tmph_, *ffh_, *wb_;
    cudaGetSymbolAddress((void**)&h_,    g_h);
    cudaGetSymbolAddress((void**)&hh_,   g_hh);
    cudaGetSymbolAddress((void**)&qkvh_, g_qkvh);
    cudaGetSymbolAddress((void**)&atth_, g_atth);
    cudaGetSymbolAddress((void**)&tmph_, g_tmph);
    cudaGetSymbolAddress((void**)&ffh_,  g_ffh);
    cudaGetSymbolAddress((void**)&wb_,   g_wb);

    cudaFuncSetAttribute(gemm_tc, cudaFuncAttributeMaxDynamicSharedMemorySize, SMEM_GEMM);

    const int M = MTOT;

    // convert all weights to fp16 [N,K]: 4 batched launches (grid.z = layer)
    wconv<<<dim3(1536/32, 512/32, 10), dim3(32,8)>>>(Wqkv, wb_,
        512, 1536, (size_t)512*1536, WB_PER_LAYER);
    wconv<<<dim3(512/32, 512/32, 10), dim3(32,8)>>>(Wo, wb_ + 786432,
        512, 512, (size_t)512*512, WB_PER_LAYER);
    wconv<<<dim3(2048/32, 512/32, 10), dim3(32,8)>>>(W1, wb_ + 1048576,
        512, 2048, (size_t)512*2048, WB_PER_LAYER);
    wconv<<<dim3(512/32, 2048/32, 10), dim3(32,8)>>>(W2, wb_ + 2097152,
        2048, 512, (size_t)2048*512, WB_PER_LAYER);

    embed_enc<<<(BB*SPD*DD + 255)/256, 256>>>(x, W_data, b_data, emb_in);

    for (int i = 0; i < 10; i++) {
        const int* rnd = (i < 5) ? rand_enc : rand_dec;
        int nb = (i < 5) ? 129 : 128;
        int S  = (i < 5) ? 1025 : 1024;
        size_t L = (size_t)i * WB_PER_LAYER;

        gemm_tc<<<dim3(12, M/128), 256, SMEM_GEMM>>>(hh_, wb_ + L,
            bqkv + (size_t)i*1536, qkvh_, 1536, 512, 2);
        attn_kernel<<<dim3(nb, HH, BB), 256>>>(qkvh_, atth_, rnd, nb, S);
        gemm_tc<<<dim3(4, M/128), 256, SMEM_GEMM>>>(atth_, wb_ + L + 786432,
            bo + (size_t)i*512, tmph_, 512, 512, 2);
        add_ln<<<M, 256>>>(h_, hh_, tmph_, ln1_g + (size_t)i*DD, ln1_b + (size_t)i*DD);
        gemm_tc<<<dim3(16, M/128), 256, SMEM_GEMM>>>(hh_, wb_ + L + 1048576,
            b1 + (size_t)i*FFD, ffh_, 2048, 512, 1);
        gemm_tc<<<dim3(4, M/128), 256, SMEM_GEMM>>>(ffh_, wb_ + L + 2097152,
            b2 + (size_t)i*512, tmph_, 512, 2048, 2);
        add_ln<<<M, 256>>>(h_, hh_, tmph_, ln2_g + (size_t)i*DD, ln2_b + (size_t)i*DD);

        if (i == 4) {
            latent<<<BB, 16>>>(W_mean, b_mean, W_lv, b_lv, eps);
            seq_expand<<<(BB*2*MSEQ + 255)/256, 256>>>(W_exp, b_exp);
            dec_init<<<(BB*MSEQ*DD + 255)/256, 256>>>(W_conv, b_conv, emb_out);
            zero_pad_rows<<<(BB*(SPD-MSEQ)*DD + 255)/256, 256>>>();
        }
    }

    out_proj<<<(BB*MSEQ*16 + 255)/256, 256>>>(W_seq, b_seq, (float*)d_out);
    elbo_fin<<<1, 32>>>((float*)d_out, out_size);
}